// round 12
// baseline (speedup 1.0000x reference)
#include <cuda_runtime.h>
#include <cuda_fp16.h>
#include <cuda_bf16.h>
#include <math.h>
#include <stdint.h>

#define Bb 4
#define TQn 2048
#define Tn 2048
#define En 2048
#define Hn 16
#define Dn 128
#define HDn 2048
#define NTOK 8192
#define POSN 4096

// ---------------- scratch ----------------------------------------------------
__device__ float g_cos[POSN * 64];
__device__ float g_sin[POSN * 64];
__device__ int   g_kind;
__device__ int   g_sel[NTOK];
__device__ int   g_nkeep[Bb];

__device__ __half g_xh[(size_t)NTOK * En];
__device__ __half g_xl[(size_t)NTOK * En];
__device__ __half g_ah[(size_t)NTOK * En];
__device__ __half g_al[(size_t)NTOK * En];
__device__ __half g_qh[(size_t)NTOK * HDn];
__device__ __half g_ql[(size_t)NTOK * HDn];
__device__ __half g_kh[(size_t)NTOK * HDn];
__device__ __half g_vh[(size_t)NTOK * HDn];
__device__ __half g_yh[(size_t)NTOK * HDn];
__device__ __half g_yl[(size_t)NTOK * HDn];
__device__ __half g_wq[(size_t)En * HDn];
__device__ __half g_wk[(size_t)En * HDn];
__device__ __half g_wv[(size_t)En * HDn];
__device__ __half g_wo[(size_t)En * HDn];

// ---------------- helpers ----------------------------------------------------
__device__ __forceinline__ float neginf() { return __int_as_float(0xff800000u); }

__device__ __forceinline__ uint32_t smem_u32(const void* p) {
    uint32_t a;
    asm("{ .reg .u64 t; cvta.to.shared.u64 t, %1; cvt.u32.u64 %0, t; }" : "=r"(a) : "l"(p));
    return a;
}
__device__ __forceinline__ void mma16816(float* d, const uint32_t* a, const uint32_t* b) {
    asm volatile("mma.sync.aligned.m16n8k16.row.col.f32.f16.f16.f32 "
        "{%0,%1,%2,%3}, {%4,%5,%6,%7}, {%8,%9}, {%0,%1,%2,%3};"
        : "+f"(d[0]), "+f"(d[1]), "+f"(d[2]), "+f"(d[3])
        : "r"(a[0]), "r"(a[1]), "r"(a[2]), "r"(a[3]), "r"(b[0]), "r"(b[1]));
}
__device__ __forceinline__ void ldm4(uint32_t* r, uint32_t a) {
    asm volatile("ldmatrix.sync.aligned.m8n8.x4.shared.b16 {%0,%1,%2,%3}, [%4];"
        : "=r"(r[0]), "=r"(r[1]), "=r"(r[2]), "=r"(r[3]) : "r"(a));
}
__device__ __forceinline__ void ldm4t(uint32_t* r, uint32_t a) {
    asm volatile("ldmatrix.sync.aligned.m8n8.x4.trans.shared.b16 {%0,%1,%2,%3}, [%4];"
        : "=r"(r[0]), "=r"(r[1]), "=r"(r[2]), "=r"(r[3]) : "r"(a));
}
__device__ __forceinline__ void cpa16(uint32_t d, const void* s) {
    asm volatile("cp.async.cg.shared.global [%0], [%1], 16;" :: "r"(d), "l"(s));
}
#define CP_COMMIT() asm volatile("cp.async.commit_group;" ::: "memory")
#define CP_WAIT1()  asm volatile("cp.async.wait_group 1;" ::: "memory")

__device__ __forceinline__ void split2h(float a, float b, uint32_t& hi, uint32_t& lo) {
    __half2 h = __floats2half2_rn(a, b);
    hi = *(uint32_t*)&h;
    __half2 l = __floats2half2_rn(a - __low2float(h), b - __high2float(h));
    lo = *(uint32_t*)&l;
}

__device__ __forceinline__ bool mask_at(const void* m, int i, int k) {
    if (k == 0) return ((const unsigned char*)m)[i] != 0;
    if (k == 1) return ((const int*)m)[i] != 0;
    if (k == 2) return ((const float*)m)[i] != 0.0f;
    return __bfloat162float(((const __nv_bfloat16*)m)[i]) != 0.0f;
}

// ---------------- small kernels ---------------------------------------------
__global__ void ropetab_kernel() {
    int t = blockIdx.x * 256 + threadIdx.x;
    if (t >= POSN * 64) return;
    int j = t & 63, p = t >> 6;
    double inv = 1.0 / pow(10000.0, (double)(2 * j) / 128.0);
    float invf = (float)inv;
    float ang = (float)p * invf;
    g_cos[t] = (float)cos((double)ang);
    g_sin[t] = (float)sin((double)ang);
}

__global__ void sniff_kernel(const unsigned char* m) {
    __shared__ int f[3];
    if (threadIdx.x < 3) f[threadIdx.x] = 0;
    __syncthreads();
    int a = 0, b = 0, c = 0;
    for (int i = threadIdx.x; i < Bb * Tn; i += 256) {
        unsigned v = m[i];
        if (v > 1) a = 1;
        if (v != 0 && (i & 3)) b = 1;
        if (v != 0 && ((i & 3) < 2)) c = 1;
    }
    if (a) atomicOr(&f[0], 1);
    if (b) atomicOr(&f[1], 1);
    if (c) atomicOr(&f[2], 1);
    __syncthreads();
    if (threadIdx.x == 0)
        g_kind = (!f[0]) ? (f[1] ? 0 : 1) : (f[2] ? 3 : 2);
}

__global__ void selbuild_kernel(const void* m) {
    __shared__ int sc[1024];
    __shared__ int stot;
    int b = blockIdx.x, tid = threadIdx.x;
    int kind = g_kind;
    int i0 = tid * 2, i1 = i0 + 1;
    int k0 = mask_at(m, b * Tn + i0, kind) ? 0 : 1;
    int k1 = mask_at(m, b * Tn + i1, kind) ? 0 : 1;
    int part = k0 + k1;
    sc[tid] = part;
    __syncthreads();
    for (int off = 1; off < 1024; off <<= 1) {
        int v = (tid >= off) ? sc[tid - off] : 0;
        __syncthreads();
        sc[tid] += v;
        __syncthreads();
    }
    int base = sc[tid] - part;
    if (k0) g_sel[b * Tn + base] = b * Tn + i0;
    if (k1) g_sel[b * Tn + base + k0] = b * Tn + i1;
    if (tid == 1023) { g_nkeep[b] = sc[1023]; stot = sc[1023]; }
    __syncthreads();
    for (int i = stot + tid; i < Tn; i += 1024) g_sel[b * Tn + i] = b * Tn;
}

__global__ void splitH2_kernel(const float* __restrict__ in,
                               __half* __restrict__ hi, __half* __restrict__ lo,
                               int n4) {
    int i = blockIdx.x * 256 + threadIdx.x;
    if (i >= n4) return;
    float4 v = ((const float4*)in)[i];
    uint32_t h0, l0, h1, l1;
    split2h(v.x, v.y, h0, l0);
    split2h(v.z, v.w, h1, l1);
    ((uint32_t*)hi)[i * 2]     = h0;
    ((uint32_t*)hi)[i * 2 + 1] = h1;
    ((uint32_t*)lo)[i * 2]     = l0;
    ((uint32_t*)lo)[i * 2 + 1] = l1;
}

__global__ void splitT_kernel(const float* __restrict__ W, __half* __restrict__ out,
                              int perm) {
    __shared__ float t[32][33];
    int n0 = blockIdx.x * 32, k0 = blockIdx.y * 32;
    for (int r = threadIdx.y; r < 32; r += 8)
        t[r][threadIdx.x] = W[(size_t)(k0 + r) * 2048 + n0 + threadIdx.x];
    __syncthreads();
    for (int r = threadIdx.y; r < 32; r += 8) {
        int n = n0 + r;
        int rr = n & 127;
        int nout = perm ? ((n & ~127) | (rr < 64 ? (rr * 2) : ((rr - 64) * 2 + 1))) : n;
        out[(size_t)nout * 2048 + k0 + threadIdx.x] = __float2half(t[threadIdx.x][r]);
    }
}

// ---------------- HMMA fp16x2 GEMM with fused epilogues ----------------------
#define GROW 80
#define GTILE 10240
#define GST  30720
#define GSMEM (3 * GST)

template<int MODE>
__global__ __launch_bounds__(256, 2) void bgemm_kernel(
    const __half* __restrict__ Ahi, const __half* __restrict__ Alo,
    const __half* __restrict__ Bh, float* __restrict__ Cf,
    __half* __restrict__ Oh, __half* __restrict__ Ol,
    const int* __restrict__ Asel, const int* __restrict__ pos,
    const int* __restrict__ nkp, int M, int N, int K) {
    extern __shared__ __align__(128) char gsm[];
    uint32_t sb = smem_u32(gsm);
    int tid = threadIdx.x, lane = tid & 31, wid = tid >> 5;
    int wm = wid & 1, wn = wid >> 1;
    size_t bm = (size_t)blockIdx.y * 128, bn = (size_t)blockIdx.x * 128;

    if (nkp != nullptr) {
        if ((int)(bm & (Tn - 1)) >= nkp[bm >> 11]) return;
    }

    const __half* srcb[6];
    uint32_t dstb[6];
#pragma unroll
    for (int i = 0; i < 6; i++) {
        int id = tid + i * 256, tile = id >> 9, w = id & 511, row = w >> 2, c = w & 3;
        const __half* base = (tile == 0) ? Ahi : (tile == 1) ? Alo : Bh;
        size_t grow;
        if (tile < 2) grow = Asel ? (size_t)Asel[bm + row] : (bm + row);
        else          grow = bn + row;
        srcb[i] = base + grow * (size_t)K + c * 8;
        dstb[i] = sb + tile * GTILE + row * GROW + c * 16;
    }

    float acc[4][4][4];
#pragma unroll
    for (int a = 0; a < 4; a++)
#pragma unroll
        for (int b = 0; b < 4; b++)
#pragma unroll
            for (int c = 0; c < 4; c++) acc[a][b][c] = 0.f;

    const int NT = K / 32;
#pragma unroll
    for (int s = 0; s < 2; s++) {
#pragma unroll
        for (int i = 0; i < 6; i++) cpa16(dstb[i] + s * GST, srcb[i] + s * 32);
        CP_COMMIT();
    }

    for (int kt = 0; kt < NT; kt++) {
        CP_WAIT1();
        __syncthreads();
        if (kt + 2 < NT) {
            uint32_t so = ((kt + 2) % 3) * GST;
#pragma unroll
            for (int i = 0; i < 6; i++) cpa16(dstb[i] + so, srcb[i] + (kt + 2) * 32);
        }
        CP_COMMIT();

        uint32_t st = sb + (kt % 3) * GST;
        uint32_t arow = st + (wm * 64 + (lane & 15)) * GROW + ((lane >> 4) << 4);
        uint32_t brow = st + 2 * GTILE +
                        (wn * 32 + (lane & 7) + ((lane >> 4) << 3)) * GROW +
                        (((lane >> 3) & 1) << 4);
#pragma unroll
        for (int kf = 0; kf < 2; kf++) {
            uint32_t ah[4][4], al[4][4];
#pragma unroll
            for (int mi = 0; mi < 4; mi++) {
                ldm4(ah[mi], arow + mi * 16 * GROW + kf * 32);
                ldm4(al[mi], arow + GTILE + mi * 16 * GROW + kf * 32);
            }
#pragma unroll
            for (int njp = 0; njp < 2; njp++) {
                uint32_t bh[4];
                ldm4(bh, brow + njp * 16 * GROW + kf * 32);
#pragma unroll
                for (int mi = 0; mi < 4; mi++) {
                    mma16816(acc[mi][2 * njp],     ah[mi], bh);
                    mma16816(acc[mi][2 * njp],     al[mi], bh);
                    mma16816(acc[mi][2 * njp + 1], ah[mi], bh + 2);
                    mma16816(acc[mi][2 * njp + 1], al[mi], bh + 2);
                }
            }
        }
        __syncthreads();
    }

#pragma unroll
    for (int mi = 0; mi < 4; mi++) {
        size_t r0 = bm + wm * 64 + mi * 16 + (lane >> 2);
        size_t r1 = r0 + 8;
        int p0 = 0, p1 = 0;
        if (MODE == 1 || MODE == 2) {
            p0 = pos[Asel ? Asel[r0] : (int)r0];
            p1 = pos[Asel ? Asel[r1] : (int)r1];
        }
#pragma unroll
        for (int nj = 0; nj < 4; nj++) {
            size_t cc = bn + wn * 32 + nj * 8 + (lane & 3) * 2;
            float a0 = acc[mi][nj][0], b0 = acc[mi][nj][1];
            float a1 = acc[mi][nj][2], b1 = acc[mi][nj][3];
            if (MODE == 0) {
                *(float2*)&Cf[r0 * N + cc] = make_float2(a0, b0);
                *(float2*)&Cf[r1 * N + cc] = make_float2(a1, b1);
            } else if (MODE == 3) {
                *(__half2*)&Oh[r0 * N + cc] = __floats2half2_rn(a0, b0);
                *(__half2*)&Oh[r1 * N + cc] = __floats2half2_rn(a1, b1);
            } else {
                int j = ((int)cc & 127) >> 1;
                float c0 = g_cos[p0 * 64 + j], s0 = g_sin[p0 * 64 + j];
                float c1 = g_cos[p1 * 64 + j], s1 = g_sin[p1 * 64 + j];
                float e0 = a0 * c0 - b0 * s0, o0 = b0 * c0 + a0 * s0;
                float e1 = a1 * c1 - b1 * s1, o1 = b1 * c1 + a1 * s1;
                if (MODE == 1) {
                    uint32_t h, l;
                    split2h(e0, o0, h, l);
                    *(uint32_t*)&Oh[r0 * N + cc] = h;
                    *(uint32_t*)&Ol[r0 * N + cc] = l;
                    split2h(e1, o1, h, l);
                    *(uint32_t*)&Oh[r1 * N + cc] = h;
                    *(uint32_t*)&Ol[r1 * N + cc] = l;
                } else {
                    *(__half2*)&Oh[r0 * N + cc] = __floats2half2_rn(e0, o0);
                    *(__half2*)&Oh[r1 * N + cc] = __floats2half2_rn(e1, o1);
                }
            }
        }
    }
}

// ---------------- HMMA flash attention: 64q x 64k, 4 warps (R9 config) -------
#define ATQ 272
#define S_QH 0
#define S_QL 17408
#define S_K  34816
#define S_V  52224
#define ATTN_SMEM 69632

__global__ __launch_bounds__(128) void attn_kernel(
    const __half* __restrict__ Qh, const __half* __restrict__ Ql,
    const __half* __restrict__ Kh, const __half* __restrict__ Vh,
    __half* __restrict__ Yh, __half* __restrict__ Yl) {
    extern __shared__ __align__(128) char ash[];
    uint32_t sb = smem_u32(ash);
    int tid = threadIdx.x, lane = tid & 31, w = tid >> 5;
    int qb = blockIdx.x * 64, h = blockIdx.y, b = blockIdx.z;
    size_t tok0 = (size_t)b * TQn + qb;
    size_t ktok0 = (size_t)b * Tn;
    int hcol = h * 128;
    const float NI = neginf();
    const float scale = 0.08838834764831845f;
    const int nk = g_nkeep[b];
    const int nt = (nk + 63) >> 6;

#pragma unroll
    for (int i = 0; i < 16; i++) {
        int id = tid + i * 128;
        int buf = id >> 10, ww = id & 1023, row = ww >> 4, c = ww & 15;
        const __half* src = (buf ? Ql : Qh) + (tok0 + row) * HDn + hcol + c * 8;
        *(uint4*)(ash + (buf ? S_QL : S_QH) + row * ATQ + c * 16) = *(const uint4*)src;
    }
    __syncthreads();

    uint32_t qhf[8][4], qlf[8][4];
    {
        uint32_t abase = sb + (w * 16 + (lane & 15)) * ATQ + ((lane >> 4) << 4);
#pragma unroll
        for (int kf = 0; kf < 8; kf++) {
            ldm4(qhf[kf], abase + kf * 32);
            ldm4(qlf[kf], abase + S_QL + kf * 32);
        }
    }

    float oa[16][4];
#pragma unroll
    for (int i = 0; i < 16; i++)
#pragma unroll
        for (int j = 0; j < 4; j++) oa[i][j] = 0.f;
    float m_a = NI, m_b = NI, l_a = 0.f, l_b = 0.f;

    int crow = tid >> 4, ccol = tid & 15;
    uint32_t kdst = sb + S_K + crow * ATQ + ccol * 16;
    uint32_t vdst = sb + S_V + crow * ATQ + ccol * 16;
    const __half* ksrc0 = Kh + (ktok0 + crow) * HDn + hcol + ccol * 8;
    const __half* vsrc0 = Vh + (ktok0 + crow) * HDn + hcol + ccol * 8;

#define ISSUE_K(kt) do { \
    const __half* _s = ksrc0 + (size_t)(kt) * 64 * HDn; \
    _Pragma("unroll") for (int _i = 0; _i < 8; _i++) \
        cpa16(kdst + _i * 8 * ATQ, _s + (size_t)_i * 8 * HDn); \
} while (0)
#define ISSUE_V(kt) do { \
    const __half* _s = vsrc0 + (size_t)(kt) * 64 * HDn; \
    _Pragma("unroll") for (int _i = 0; _i < 8; _i++) \
        cpa16(vdst + _i * 8 * ATQ, _s + (size_t)_i * 8 * HDn); \
} while (0)

    ISSUE_K(0); CP_COMMIT();
    ISSUE_V(0); CP_COMMIT();

    for (int kt = 0; kt < nt; kt++) {
        CP_WAIT1();
        __syncthreads();

        // S = Q K^T
        float sc[8][4];
#pragma unroll
        for (int i = 0; i < 8; i++)
#pragma unroll
            for (int j = 0; j < 4; j++) sc[i][j] = 0.f;
        {
            uint32_t bbase = sb + S_K +
                ((lane & 7) + ((lane >> 4) << 3)) * ATQ + (((lane >> 3) & 1) << 4);
#pragma unroll
            for (int kf = 0; kf < 8; kf++) {
#pragma unroll
                for (int njp = 0; njp < 4; njp++) {
                    uint32_t kh4[4];
                    ldm4(kh4, bbase + njp * 16 * ATQ + kf * 32);
                    mma16816(sc[2 * njp],     qhf[kf], kh4);
                    mma16816(sc[2 * njp],     qlf[kf], kh4);
                    mma16816(sc[2 * njp + 1], qhf[kf], kh4 + 2);
                    mma16816(sc[2 * njp + 1], qlf[kf], kh4 + 2);
                }
            }
        }
        __syncthreads();
        ISSUE_K((kt + 1) & 31); CP_COMMIT();

        // validity from compaction (register compare)
        float ta = NI, tb = NI;
        bool v0[8], v1[8];
#pragma unroll
        for (int nf = 0; nf < 8; nf++) {
            int key0 = kt * 64 + nf * 8 + ((lane & 3) << 1);
            v0[nf] = key0 < nk;
            v1[nf] = key0 + 1 < nk;
#pragma unroll
            for (int j = 0; j < 4; j++) sc[nf][j] *= scale;
            if (v0[nf]) { ta = fmaxf(ta, sc[nf][0]); tb = fmaxf(tb, sc[nf][2]); }
            if (v1[nf]) { ta = fmaxf(ta, sc[nf][1]); tb = fmaxf(tb, sc[nf][3]); }
        }
        ta = fmaxf(ta, __shfl_xor_sync(0xffffffffu, ta, 1));
        ta = fmaxf(ta, __shfl_xor_sync(0xffffffffu, ta, 2));
        tb = fmaxf(tb, __shfl_xor_sync(0xffffffffu, tb, 1));
        tb = fmaxf(tb, __shfl_xor_sync(0xffffffffu, tb, 2));
        float mna = fmaxf(m_a, ta), mnb = fmaxf(m_b, tb);
        float alpha_a = (m_a > NI) ? __expf(m_a - mna) : 1.f;
        float alpha_b = (m_b > NI) ? __expf(m_b - mnb) : 1.f;
        m_a = mna; m_b = mnb;

        float sa = 0.f, sbm = 0.f;
#pragma unroll
        for (int nf = 0; nf < 8; nf++) {
            float p0 = (!v0[nf] || m_a == NI) ? 0.f : __expf(sc[nf][0] - m_a);
            float p1 = (!v1[nf] || m_a == NI) ? 0.f : __expf(sc[nf][1] - m_a);
            float p2 = (!v0[nf] || m_b == NI) ? 0.f : __expf(sc[nf][2] - m_b);
            float p3 = (!v1[nf] || m_b == NI) ? 0.f : __expf(sc[nf][3] - m_b);
            sc[nf][0] = p0; sc[nf][1] = p1; sc[nf][2] = p2; sc[nf][3] = p3;
            sa += p0 + p1; sbm += p2 + p3;
        }
        sa  += __shfl_xor_sync(0xffffffffu, sa, 1);
        sa  += __shfl_xor_sync(0xffffffffu, sa, 2);
        sbm += __shfl_xor_sync(0xffffffffu, sbm, 1);
        sbm += __shfl_xor_sync(0xffffffffu, sbm, 2);
        l_a = l_a * alpha_a + sa;
        l_b = l_b * alpha_b + sbm;
#pragma unroll
        for (int nf = 0; nf < 16; nf++) {
            oa[nf][0] *= alpha_a; oa[nf][1] *= alpha_a;
            oa[nf][2] *= alpha_b; oa[nf][3] *= alpha_b;
        }

        uint32_t ph[4][4], pl[4][4];
#pragma unroll
        for (int t = 0; t < 4; t++) {
            split2h(sc[2 * t][0],     sc[2 * t][1],     ph[t][0], pl[t][0]);
            split2h(sc[2 * t][2],     sc[2 * t][3],     ph[t][1], pl[t][1]);
            split2h(sc[2 * t + 1][0], sc[2 * t + 1][1], ph[t][2], pl[t][2]);
            split2h(sc[2 * t + 1][2], sc[2 * t + 1][3], ph[t][3], pl[t][3]);
        }

        CP_WAIT1();
        __syncthreads();

        // O += P V
        {
            uint32_t vbase = sb + S_V +
                ((lane & 7) + (((lane >> 3) & 1) << 3)) * ATQ + ((lane >> 4) << 4);
#pragma unroll
            for (int t = 0; t < 4; t++) {
#pragma unroll
                for (int njp = 0; njp < 8; njp++) {
                    uint32_t vh4[4];
                    ldm4t(vh4, vbase + t * 16 * ATQ + njp * 32);
                    int n0 = njp * 2, n1 = n0 + 1;
                    mma16816(oa[n0], ph[t], vh4);
                    mma16816(oa[n0], pl[t], vh4);
                    mma16816(oa[n1], ph[t], vh4 + 2);
                    mma16816(oa[n1], pl[t], vh4 + 2);
                }
            }
        }
        __syncthreads();
        ISSUE_V((kt + 1) & 31); CP_COMMIT();
    }

    float ia = 1.f / l_a, ib = 1.f / l_b;
    size_t ra = (tok0 + w * 16 + (lane >> 2)) * HDn + hcol + (lane & 3) * 2;
#pragma unroll
    for (int nf = 0; nf < 16; nf++) {
        uint32_t hh, ll;
        split2h(oa[nf][0] * ia, oa[nf][1] * ia, hh, ll);
        *(uint32_t*)&Yh[ra + nf * 8] = hh;
        *(uint32_t*)&Yl[ra + nf * 8] = ll;
        split2h(oa[nf][2] * ib, oa[nf][3] * ib, hh, ll);
        *(uint32_t*)&Yh[ra + 8 * HDn + nf * 8] = hh;
        *(uint32_t*)&Yl[ra + 8 * HDn + nf * 8] = ll;
    }
}

// ---------------- launch -----------------------------------------------------
extern "C" void kernel_launch(void* const* d_in, const int* in_sizes, int n_in,
                              void* d_out, int out_size) {
    const float* x       = (const float*)d_in[0];
    const float* xall    = (const float*)d_in[1];
    const int*   posx    = (const int*)d_in[2];
    const int*   posxall = (const int*)d_in[3];
    const void*  mask    = d_in[4];
    const float* Wq      = (const float*)d_in[5];
    const float* Wk      = (const float*)d_in[6];
    const float* Wv      = (const float*)d_in[7];
    const float* Wo      = (const float*)d_in[8];
    float* out = (float*)d_out;

    __half *xh, *xl, *ah, *al, *qh, *ql, *kh, *vh, *yh, *yl, *wq, *wk, *wv, *wo;
    int *sel, *nkp;
    cudaGetSymbolAddress((void**)&xh, g_xh);
    cudaGetSymbolAddress((void**)&xl, g_xl);
    cudaGetSymbolAddress((void**)&ah, g_ah);
    cudaGetSymbolAddress((void**)&al, g_al);
    cudaGetSymbolAddress((void**)&qh, g_qh);
    cudaGetSymbolAddress((void**)&ql, g_ql);
    cudaGetSymbolAddress((void**)&kh, g_kh);
    cudaGetSymbolAddress((void**)&vh, g_vh);
    cudaGetSymbolAddress((void**)&yh, g_yh);
    cudaGetSymbolAddress((void**)&yl, g_yl);
    cudaGetSymbolAddress((void**)&wq, g_wq);
    cudaGetSymbolAddress((void**)&wk, g_wk);
    cudaGetSymbolAddress((void**)&wv, g_wv);
    cudaGetSymbolAddress((void**)&wo, g_wo);
    cudaGetSymbolAddress((void**)&sel, g_sel);
    cudaGetSymbolAddress((void**)&nkp, g_nkeep);

    cudaFuncSetAttribute(bgemm_kernel<0>, cudaFuncAttributeMaxDynamicSharedMemorySize, GSMEM);
    cudaFuncSetAttribute(bgemm_kernel<1>, cudaFuncAttributeMaxDynamicSharedMemorySize, GSMEM);
    cudaFuncSetAttribute(bgemm_kernel<2>, cudaFuncAttributeMaxDynamicSharedMemorySize, GSMEM);
    cudaFuncSetAttribute(bgemm_kernel<3>, cudaFuncAttributeMaxDynamicSharedMemorySize, GSMEM);
    cudaFuncSetAttribute(attn_kernel, cudaFuncAttributeMaxDynamicSharedMemorySize, ATTN_SMEM);

    static cudaStream_t s1 = nullptr, s2 = nullptr;
    static cudaEvent_t ev0 = nullptr, evPre = nullptr, ev1 = nullptr, ev2 = nullptr, evWo = nullptr;
    if (s1 == nullptr) {
        cudaStreamCreateWithFlags(&s1, cudaStreamNonBlocking);
        cudaStreamCreateWithFlags(&s2, cudaStreamNonBlocking);
        cudaEventCreateWithFlags(&ev0,  cudaEventDisableTiming);
        cudaEventCreateWithFlags(&evPre, cudaEventDisableTiming);
        cudaEventCreateWithFlags(&ev1,  cudaEventDisableTiming);
        cudaEventCreateWithFlags(&ev2,  cudaEventDisableTiming);
        cudaEventCreateWithFlags(&evWo, cudaEventDisableTiming);
    }

    // fork
    cudaEventRecord(ev0, 0);
    cudaStreamWaitEvent(s1, ev0, 0);
    cudaStreamWaitEvent(s2, ev0, 0);

    // s0: rope tables + mask analysis (the only cross-path prologue deps)
    ropetab_kernel<<<(POSN * 64 + 255) / 256, 256>>>();
    sniff_kernel<<<1, 256>>>((const unsigned char*)mask);
    selbuild_kernel<<<Bb, 1024>>>(mask);
    cudaEventRecord(evPre, 0);

    const int NE4 = NTOK * En / 4;
    dim3 gt(64, 64), bt(32, 8);
    dim3 gg(HDn / 128, NTOK / 128);

    // s1: Q path, then Wo transpose (off critical path until out-proj)
    splitH2_kernel<<<(NE4 + 255) / 256, 256, 0, s1>>>(x, xh, xl, NE4);
    splitT_kernel<<<gt, bt, 0, s1>>>(Wq, wq, 1);
    cudaStreamWaitEvent(s1, evPre, 0);
    bgemm_kernel<1><<<gg, 256, GSMEM, s1>>>(xh, xl, wq, nullptr, qh, ql,
                                            nullptr, posx, nullptr, NTOK, HDn, En);
    cudaEventRecord(ev1, s1);
    splitT_kernel<<<gt, bt, 0, s1>>>(Wo, wo, 0);
    cudaEventRecord(evWo, s1);

    // s2: K/V path
    splitH2_kernel<<<(NE4 + 255) / 256, 256, 0, s2>>>(xall, ah, al, NE4);
    splitT_kernel<<<gt, bt, 0, s2>>>(Wk, wk, 1);
    splitT_kernel<<<gt, bt, 0, s2>>>(Wv, wv, 0);
    cudaStreamWaitEvent(s2, evPre, 0);
    bgemm_kernel<2><<<gg, 256, GSMEM, s2>>>(ah, al, wk, nullptr, kh, nullptr,
                                            sel, posxall, nkp, NTOK, HDn, En);
    bgemm_kernel<3><<<gg, 256, GSMEM, s2>>>(ah, al, wv, nullptr, vh, nullptr,
                                            sel, nullptr, nkp, NTOK, HDn, En);
    cudaEventRecord(ev2, s2);

    // join
    cudaStreamWaitEvent(0, ev1, 0);
    cudaStreamWaitEvent(0, ev2, 0);

    dim3 ga(TQn / 64, Hn, Bb);
    attn_kernel<<<ga, 128, ATTN_SMEM>>>(qh, ql, kh, vh, yh, yl);

    cudaStreamWaitEvent(0, evWo, 0);
    dim3 go(En / 128, NTOK / 128);
    bgemm_kernel<0><<<go, 256, GSMEM>>>(yh, yl, wo, out, nullptr, nullptr,
                                        nullptr, nullptr, nullptr, NTOK, En, HDn);
}

// round 13
// speedup vs baseline: 1.4169x; 1.4169x over previous
#include <cuda_runtime.h>
#include <cuda_fp16.h>
#include <cuda_bf16.h>
#include <math.h>
#include <stdint.h>

#define Bb 4
#define TQn 2048
#define Tn 2048
#define En 2048
#define Hn 16
#define Dn 128
#define HDn 2048
#define NTOK 8192
#define POSN 4096

// ---------------- scratch ----------------------------------------------------
__device__ float g_cos[POSN * 64];
__device__ float g_sin[POSN * 64];
__device__ int   g_kind;
__device__ int   g_sel[NTOK];
__device__ int   g_nkeep[Bb];

__device__ __half g_xh[(size_t)NTOK * En];
__device__ __half g_xl[(size_t)NTOK * En];
__device__ __half g_ah[(size_t)NTOK * En];
__device__ __half g_al[(size_t)NTOK * En];
__device__ __half g_qh[(size_t)NTOK * HDn];
__device__ __half g_ql[(size_t)NTOK * HDn];
__device__ __half g_kh[(size_t)NTOK * HDn];
__device__ __half g_vh[(size_t)NTOK * HDn];
__device__ __half g_yh[(size_t)NTOK * HDn];
__device__ __half g_yl[(size_t)NTOK * HDn];
__device__ __half g_wq[(size_t)En * HDn];
__device__ __half g_wk[(size_t)En * HDn];
__device__ __half g_wv[(size_t)En * HDn];
__device__ __half g_wo[(size_t)En * HDn];

// ---------------- helpers ----------------------------------------------------
__device__ __forceinline__ float neginf() { return __int_as_float(0xff800000u); }

__device__ __forceinline__ uint32_t smem_u32(const void* p) {
    uint32_t a;
    asm("{ .reg .u64 t; cvta.to.shared.u64 t, %1; cvt.u32.u64 %0, t; }" : "=r"(a) : "l"(p));
    return a;
}
__device__ __forceinline__ void mma16816(float* d, const uint32_t* a, const uint32_t* b) {
    asm volatile("mma.sync.aligned.m16n8k16.row.col.f32.f16.f16.f32 "
        "{%0,%1,%2,%3}, {%4,%5,%6,%7}, {%8,%9}, {%0,%1,%2,%3};"
        : "+f"(d[0]), "+f"(d[1]), "+f"(d[2]), "+f"(d[3])
        : "r"(a[0]), "r"(a[1]), "r"(a[2]), "r"(a[3]), "r"(b[0]), "r"(b[1]));
}
__device__ __forceinline__ void ldm4(uint32_t* r, uint32_t a) {
    asm volatile("ldmatrix.sync.aligned.m8n8.x4.shared.b16 {%0,%1,%2,%3}, [%4];"
        : "=r"(r[0]), "=r"(r[1]), "=r"(r[2]), "=r"(r[3]) : "r"(a));
}
__device__ __forceinline__ void ldm4t(uint32_t* r, uint32_t a) {
    asm volatile("ldmatrix.sync.aligned.m8n8.x4.trans.shared.b16 {%0,%1,%2,%3}, [%4];"
        : "=r"(r[0]), "=r"(r[1]), "=r"(r[2]), "=r"(r[3]) : "r"(a));
}
__device__ __forceinline__ void cpa16(uint32_t d, const void* s) {
    asm volatile("cp.async.cg.shared.global [%0], [%1], 16;" :: "r"(d), "l"(s));
}
#define CP_COMMIT() asm volatile("cp.async.commit_group;" ::: "memory")
#define CP_WAIT1()  asm volatile("cp.async.wait_group 1;" ::: "memory")

__device__ __forceinline__ void split2h(float a, float b, uint32_t& hi, uint32_t& lo) {
    __half2 h = __floats2half2_rn(a, b);
    hi = *(uint32_t*)&h;
    __half2 l = __floats2half2_rn(a - __low2float(h), b - __high2float(h));
    lo = *(uint32_t*)&l;
}

__device__ __forceinline__ bool mask_at(const void* m, int i, int k) {
    if (k == 0) return ((const unsigned char*)m)[i] != 0;
    if (k == 1) return ((const int*)m)[i] != 0;
    if (k == 2) return ((const float*)m)[i] != 0.0f;
    return __bfloat162float(((const __nv_bfloat16*)m)[i]) != 0.0f;
}

// ---------------- small kernels ---------------------------------------------
__global__ void ropetab_kernel() {
    int t = blockIdx.x * 256 + threadIdx.x;
    if (t >= POSN * 64) return;
    int j = t & 63, p = t >> 6;
    double inv = 1.0 / pow(10000.0, (double)(2 * j) / 128.0);
    float invf = (float)inv;
    float ang = (float)p * invf;
    g_cos[t] = (float)cos((double)ang);
    g_sin[t] = (float)sin((double)ang);
}

__global__ void sniff_kernel(const unsigned char* m) {
    __shared__ int f[3];
    if (threadIdx.x < 3) f[threadIdx.x] = 0;
    __syncthreads();
    int a = 0, b = 0, c = 0;
    for (int i = threadIdx.x; i < Bb * Tn; i += 256) {
        unsigned v = m[i];
        if (v > 1) a = 1;
        if (v != 0 && (i & 3)) b = 1;
        if (v != 0 && ((i & 3) < 2)) c = 1;
    }
    if (a) atomicOr(&f[0], 1);
    if (b) atomicOr(&f[1], 1);
    if (c) atomicOr(&f[2], 1);
    __syncthreads();
    if (threadIdx.x == 0)
        g_kind = (!f[0]) ? (f[1] ? 0 : 1) : (f[2] ? 3 : 2);
}

__global__ void selbuild_kernel(const void* m) {
    __shared__ int sc[1024];
    __shared__ int stot;
    int b = blockIdx.x, tid = threadIdx.x;
    int kind = g_kind;
    int i0 = tid * 2, i1 = i0 + 1;
    int k0 = mask_at(m, b * Tn + i0, kind) ? 0 : 1;
    int k1 = mask_at(m, b * Tn + i1, kind) ? 0 : 1;
    int part = k0 + k1;
    sc[tid] = part;
    __syncthreads();
    for (int off = 1; off < 1024; off <<= 1) {
        int v = (tid >= off) ? sc[tid - off] : 0;
        __syncthreads();
        sc[tid] += v;
        __syncthreads();
    }
    int base = sc[tid] - part;
    if (k0) g_sel[b * Tn + base] = b * Tn + i0;
    if (k1) g_sel[b * Tn + base + k0] = b * Tn + i1;
    if (tid == 1023) { g_nkeep[b] = sc[1023]; stot = sc[1023]; }
    __syncthreads();
    for (int i = stot + tid; i < Tn; i += 1024) g_sel[b * Tn + i] = b * Tn;
}

// fused: z=0 splits x -> xh/xl, z=1 splits xall -> ah/al
__global__ void splitH2x2_kernel(const float* __restrict__ x0,
                                 const float* __restrict__ x1,
                                 __half* __restrict__ h0, __half* __restrict__ l0,
                                 __half* __restrict__ h1, __half* __restrict__ l1,
                                 int n4) {
    int i = blockIdx.x * 256 + threadIdx.x;
    if (i >= n4) return;
    const float* in = blockIdx.z ? x1 : x0;
    __half* hi = blockIdx.z ? h1 : h0;
    __half* lo = blockIdx.z ? l1 : l0;
    float4 v = ((const float4*)in)[i];
    uint32_t a0, b0, a1, b1;
    split2h(v.x, v.y, a0, b0);
    split2h(v.z, v.w, a1, b1);
    ((uint32_t*)hi)[i * 2]     = a0;
    ((uint32_t*)hi)[i * 2 + 1] = a1;
    ((uint32_t*)lo)[i * 2]     = b0;
    ((uint32_t*)lo)[i * 2 + 1] = b1;
}

// fused: all four weight transposes in one launch (z selects weight)
__global__ void splitT4_kernel(const float* __restrict__ Wq, const float* __restrict__ Wk,
                               const float* __restrict__ Wv, const float* __restrict__ Wo,
                               __half* __restrict__ oq, __half* __restrict__ ok,
                               __half* __restrict__ ov, __half* __restrict__ oo) {
    __shared__ float t[32][33];
    int z = blockIdx.z;
    const float* W = (z == 0) ? Wq : (z == 1) ? Wk : (z == 2) ? Wv : Wo;
    __half* out    = (z == 0) ? oq : (z == 1) ? ok : (z == 2) ? ov : oo;
    int perm = (z < 2) ? 1 : 0;
    int n0 = blockIdx.x * 32, k0 = blockIdx.y * 32;
    for (int r = threadIdx.y; r < 32; r += 8)
        t[r][threadIdx.x] = W[(size_t)(k0 + r) * 2048 + n0 + threadIdx.x];
    __syncthreads();
    for (int r = threadIdx.y; r < 32; r += 8) {
        int n = n0 + r;
        int rr = n & 127;
        int nout = perm ? ((n & ~127) | (rr < 64 ? (rr * 2) : ((rr - 64) * 2 + 1))) : n;
        out[(size_t)nout * 2048 + k0 + threadIdx.x] = __float2half(t[threadIdx.x][r]);
    }
}

// ---------------- HMMA fp16x2 GEMM, K-tile 64, fused epilogues ---------------
#define GROW 144                 // 128B data + 16B pad (9 x 16B, coprime with 8)
#define GTILE (128 * GROW)       // 18432
#define GST   (3 * GTILE)        // 55296 per stage (Ahi, Alo, B)
#define GSMEM (3 * GST)          // 165888

template<int MODE>
__global__ __launch_bounds__(256, 1) void bgemm_kernel(
    const __half* __restrict__ Ahi, const __half* __restrict__ Alo,
    const __half* __restrict__ Bh, float* __restrict__ Cf,
    __half* __restrict__ Oh, __half* __restrict__ Ol,
    const int* __restrict__ Asel, const int* __restrict__ pos,
    const int* __restrict__ nkp, int M, int N, int K) {
    extern __shared__ __align__(128) char gsm[];
    uint32_t sb = smem_u32(gsm);
    int tid = threadIdx.x, lane = tid & 31, wid = tid >> 5;
    int wm = wid & 1, wn = wid >> 1;
    size_t bm = (size_t)blockIdx.y * 128, bn = (size_t)blockIdx.x * 128;

    if (nkp != nullptr) {
        if ((int)(bm & (Tn - 1)) >= nkp[bm >> 11]) return;
    }

    // 12 chunks of 16B per thread per stage (3 tiles x 128 rows x 8 chunks)
    const __half* srcb[12];
    uint32_t dstb[12];
#pragma unroll
    for (int i = 0; i < 12; i++) {
        int id = tid + i * 256, tile = id >> 10, w = id & 1023, row = w >> 3, c = w & 7;
        const __half* base = (tile == 0) ? Ahi : (tile == 1) ? Alo : Bh;
        size_t grow;
        if (tile < 2) grow = Asel ? (size_t)Asel[bm + row] : (bm + row);
        else          grow = bn + row;
        srcb[i] = base + grow * (size_t)K + c * 8;
        dstb[i] = sb + tile * GTILE + row * GROW + c * 16;
    }

    float acc[4][4][4];
#pragma unroll
    for (int a = 0; a < 4; a++)
#pragma unroll
        for (int b = 0; b < 4; b++)
#pragma unroll
            for (int c = 0; c < 4; c++) acc[a][b][c] = 0.f;

    const int NT = K / 64;
#pragma unroll
    for (int s = 0; s < 2; s++) {
#pragma unroll
        for (int i = 0; i < 12; i++) cpa16(dstb[i] + s * GST, srcb[i] + s * 64);
        CP_COMMIT();
    }

    for (int kt = 0; kt < NT; kt++) {
        CP_WAIT1();
        __syncthreads();
        if (kt + 2 < NT) {
            uint32_t so = ((kt + 2) % 3) * GST;
#pragma unroll
            for (int i = 0; i < 12; i++) cpa16(dstb[i] + so, srcb[i] + (kt + 2) * 64);
        }
        CP_COMMIT();

        uint32_t st = sb + (kt % 3) * GST;
        uint32_t arow = st + (wm * 64 + (lane & 15)) * GROW + ((lane >> 4) << 4);
        uint32_t brow = st + 2 * GTILE +
                        (wn * 32 + (lane & 7) + ((lane >> 4) << 3)) * GROW +
                        (((lane >> 3) & 1) << 4);
#pragma unroll
        for (int kf = 0; kf < 4; kf++) {
            uint32_t ah[4][4], al[4][4];
#pragma unroll
            for (int mi = 0; mi < 4; mi++) {
                ldm4(ah[mi], arow + mi * 16 * GROW + kf * 32);
                ldm4(al[mi], arow + GTILE + mi * 16 * GROW + kf * 32);
            }
#pragma unroll
            for (int njp = 0; njp < 2; njp++) {
                uint32_t bh[4];
                ldm4(bh, brow + njp * 16 * GROW + kf * 32);
#pragma unroll
                for (int mi = 0; mi < 4; mi++) {
                    mma16816(acc[mi][2 * njp],     ah[mi], bh);
                    mma16816(acc[mi][2 * njp],     al[mi], bh);
                    mma16816(acc[mi][2 * njp + 1], ah[mi], bh + 2);
                    mma16816(acc[mi][2 * njp + 1], al[mi], bh + 2);
                }
            }
        }
        __syncthreads();
    }

#pragma unroll
    for (int mi = 0; mi < 4; mi++) {
        size_t r0 = bm + wm * 64 + mi * 16 + (lane >> 2);
        size_t r1 = r0 + 8;
        int p0 = 0, p1 = 0;
        if (MODE == 1 || MODE == 2) {
            p0 = pos[Asel ? Asel[r0] : (int)r0];
            p1 = pos[Asel ? Asel[r1] : (int)r1];
        }
#pragma unroll
        for (int nj = 0; nj < 4; nj++) {
            size_t cc = bn + wn * 32 + nj * 8 + (lane & 3) * 2;
            float a0 = acc[mi][nj][0], b0 = acc[mi][nj][1];
            float a1 = acc[mi][nj][2], b1 = acc[mi][nj][3];
            if (MODE == 0) {
                *(float2*)&Cf[r0 * N + cc] = make_float2(a0, b0);
                *(float2*)&Cf[r1 * N + cc] = make_float2(a1, b1);
            } else if (MODE == 3) {
                *(__half2*)&Oh[r0 * N + cc] = __floats2half2_rn(a0, b0);
                *(__half2*)&Oh[r1 * N + cc] = __floats2half2_rn(a1, b1);
            } else {
                int j = ((int)cc & 127) >> 1;
                float c0 = g_cos[p0 * 64 + j], s0 = g_sin[p0 * 64 + j];
                float c1 = g_cos[p1 * 64 + j], s1 = g_sin[p1 * 64 + j];
                float e0 = a0 * c0 - b0 * s0, o0 = b0 * c0 + a0 * s0;
                float e1 = a1 * c1 - b1 * s1, o1 = b1 * c1 + a1 * s1;
                if (MODE == 1) {
                    uint32_t h, l;
                    split2h(e0, o0, h, l);
                    *(uint32_t*)&Oh[r0 * N + cc] = h;
                    *(uint32_t*)&Ol[r0 * N + cc] = l;
                    split2h(e1, o1, h, l);
                    *(uint32_t*)&Oh[r1 * N + cc] = h;
                    *(uint32_t*)&Ol[r1 * N + cc] = l;
                } else {
                    *(__half2*)&Oh[r0 * N + cc] = __floats2half2_rn(e0, o0);
                    *(__half2*)&Oh[r1 * N + cc] = __floats2half2_rn(e1, o1);
                }
            }
        }
    }
}

// ---------------- HMMA flash attention: 64q x 64k, 4 warps (R9 config) -------
#define ATQ 272
#define S_QH 0
#define S_QL 17408
#define S_K  34816
#define S_V  52224
#define ATTN_SMEM 69632

__global__ __launch_bounds__(128) void attn_kernel(
    const __half* __restrict__ Qh, const __half* __restrict__ Ql,
    const __half* __restrict__ Kh, const __half* __restrict__ Vh,
    __half* __restrict__ Yh, __half* __restrict__ Yl) {
    extern __shared__ __align__(128) char ash[];
    uint32_t sb = smem_u32(ash);
    int tid = threadIdx.x, lane = tid & 31, w = tid >> 5;
    int qb = blockIdx.x * 64, h = blockIdx.y, b = blockIdx.z;
    size_t tok0 = (size_t)b * TQn + qb;
    size_t ktok0 = (size_t)b * Tn;
    int hcol = h * 128;
    const float NI = neginf();
    const float scale = 0.08838834764831845f;
    const int nk = g_nkeep[b];
    const int nt = (nk + 63) >> 6;

#pragma unroll
    for (int i = 0; i < 16; i++) {
        int id = tid + i * 128;
        int buf = id >> 10, ww = id & 1023, row = ww >> 4, c = ww & 15;
        const __half* src = (buf ? Ql : Qh) + (tok0 + row) * HDn + hcol + c * 8;
        *(uint4*)(ash + (buf ? S_QL : S_QH) + row * ATQ + c * 16) = *(const uint4*)src;
    }
    __syncthreads();

    uint32_t qhf[8][4], qlf[8][4];
    {
        uint32_t abase = sb + (w * 16 + (lane & 15)) * ATQ + ((lane >> 4) << 4);
#pragma unroll
        for (int kf = 0; kf < 8; kf++) {
            ldm4(qhf[kf], abase + kf * 32);
            ldm4(qlf[kf], abase + S_QL + kf * 32);
        }
    }

    float oa[16][4];
#pragma unroll
    for (int i = 0; i < 16; i++)
#pragma unroll
        for (int j = 0; j < 4; j++) oa[i][j] = 0.f;
    float m_a = NI, m_b = NI, l_a = 0.f, l_b = 0.f;

    int crow = tid >> 4, ccol = tid & 15;
    uint32_t kdst = sb + S_K + crow * ATQ + ccol * 16;
    uint32_t vdst = sb + S_V + crow * ATQ + ccol * 16;
    const __half* ksrc0 = Kh + (ktok0 + crow) * HDn + hcol + ccol * 8;
    const __half* vsrc0 = Vh + (ktok0 + crow) * HDn + hcol + ccol * 8;

#define ISSUE_K(kt) do { \
    const __half* _s = ksrc0 + (size_t)(kt) * 64 * HDn; \
    _Pragma("unroll") for (int _i = 0; _i < 8; _i++) \
        cpa16(kdst + _i * 8 * ATQ, _s + (size_t)_i * 8 * HDn); \
} while (0)
#define ISSUE_V(kt) do { \
    const __half* _s = vsrc0 + (size_t)(kt) * 64 * HDn; \
    _Pragma("unroll") for (int _i = 0; _i < 8; _i++) \
        cpa16(vdst + _i * 8 * ATQ, _s + (size_t)_i * 8 * HDn); \
} while (0)

    ISSUE_K(0); CP_COMMIT();
    ISSUE_V(0); CP_COMMIT();

    for (int kt = 0; kt < nt; kt++) {
        CP_WAIT1();
        __syncthreads();

        // S = Q K^T
        float sc[8][4];
#pragma unroll
        for (int i = 0; i < 8; i++)
#pragma unroll
            for (int j = 0; j < 4; j++) sc[i][j] = 0.f;
        {
            uint32_t bbase = sb + S_K +
                ((lane & 7) + ((lane >> 4) << 3)) * ATQ + (((lane >> 3) & 1) << 4);
#pragma unroll
            for (int kf = 0; kf < 8; kf++) {
#pragma unroll
                for (int njp = 0; njp < 4; njp++) {
                    uint32_t kh4[4];
                    ldm4(kh4, bbase + njp * 16 * ATQ + kf * 32);
                    mma16816(sc[2 * njp],     qhf[kf], kh4);
                    mma16816(sc[2 * njp],     qlf[kf], kh4);
                    mma16816(sc[2 * njp + 1], qhf[kf], kh4 + 2);
                    mma16816(sc[2 * njp + 1], qlf[kf], kh4 + 2);
                }
            }
        }
        __syncthreads();
        ISSUE_K((kt + 1) & 31); CP_COMMIT();

        // validity from compaction (register compare)
        float ta = NI, tb = NI;
        bool v0[8], v1[8];
#pragma unroll
        for (int nf = 0; nf < 8; nf++) {
            int key0 = kt * 64 + nf * 8 + ((lane & 3) << 1);
            v0[nf] = key0 < nk;
            v1[nf] = key0 + 1 < nk;
#pragma unroll
            for (int j = 0; j < 4; j++) sc[nf][j] *= scale;
            if (v0[nf]) { ta = fmaxf(ta, sc[nf][0]); tb = fmaxf(tb, sc[nf][2]); }
            if (v1[nf]) { ta = fmaxf(ta, sc[nf][1]); tb = fmaxf(tb, sc[nf][3]); }
        }
        ta = fmaxf(ta, __shfl_xor_sync(0xffffffffu, ta, 1));
        ta = fmaxf(ta, __shfl_xor_sync(0xffffffffu, ta, 2));
        tb = fmaxf(tb, __shfl_xor_sync(0xffffffffu, tb, 1));
        tb = fmaxf(tb, __shfl_xor_sync(0xffffffffu, tb, 2));
        float mna = fmaxf(m_a, ta), mnb = fmaxf(m_b, tb);
        float alpha_a = (m_a > NI) ? __expf(m_a - mna) : 1.f;
        float alpha_b = (m_b > NI) ? __expf(m_b - mnb) : 1.f;
        m_a = mna; m_b = mnb;

        float sa = 0.f, sbm = 0.f;
#pragma unroll
        for (int nf = 0; nf < 8; nf++) {
            float p0 = (!v0[nf] || m_a == NI) ? 0.f : __expf(sc[nf][0] - m_a);
            float p1 = (!v1[nf] || m_a == NI) ? 0.f : __expf(sc[nf][1] - m_a);
            float p2 = (!v0[nf] || m_b == NI) ? 0.f : __expf(sc[nf][2] - m_b);
            float p3 = (!v1[nf] || m_b == NI) ? 0.f : __expf(sc[nf][3] - m_b);
            sc[nf][0] = p0; sc[nf][1] = p1; sc[nf][2] = p2; sc[nf][3] = p3;
            sa += p0 + p1; sbm += p2 + p3;
        }
        sa  += __shfl_xor_sync(0xffffffffu, sa, 1);
        sa  += __shfl_xor_sync(0xffffffffu, sa, 2);
        sbm += __shfl_xor_sync(0xffffffffu, sbm, 1);
        sbm += __shfl_xor_sync(0xffffffffu, sbm, 2);
        l_a = l_a * alpha_a + sa;
        l_b = l_b * alpha_b + sbm;
#pragma unroll
        for (int nf = 0; nf < 16; nf++) {
            oa[nf][0] *= alpha_a; oa[nf][1] *= alpha_a;
            oa[nf][2] *= alpha_b; oa[nf][3] *= alpha_b;
        }

        uint32_t ph[4][4], pl[4][4];
#pragma unroll
        for (int t = 0; t < 4; t++) {
            split2h(sc[2 * t][0],     sc[2 * t][1],     ph[t][0], pl[t][0]);
            split2h(sc[2 * t][2],     sc[2 * t][3],     ph[t][1], pl[t][1]);
            split2h(sc[2 * t + 1][0], sc[2 * t + 1][1], ph[t][2], pl[t][2]);
            split2h(sc[2 * t + 1][2], sc[2 * t + 1][3], ph[t][3], pl[t][3]);
        }

        CP_WAIT1();
        __syncthreads();

        // O += P V
        {
            uint32_t vbase = sb + S_V +
                ((lane & 7) + (((lane >> 3) & 1) << 3)) * ATQ + ((lane >> 4) << 4);
#pragma unroll
            for (int t = 0; t < 4; t++) {
#pragma unroll
                for (int njp = 0; njp < 8; njp++) {
                    uint32_t vh4[4];
                    ldm4t(vh4, vbase + t * 16 * ATQ + njp * 32);
                    int n0 = njp * 2, n1 = n0 + 1;
                    mma16816(oa[n0], ph[t], vh4);
                    mma16816(oa[n0], pl[t], vh4);
                    mma16816(oa[n1], ph[t], vh4 + 2);
                    mma16816(oa[n1], pl[t], vh4 + 2);
                }
            }
        }
        __syncthreads();
        ISSUE_V((kt + 1) & 31); CP_COMMIT();
    }

    float ia = 1.f / l_a, ib = 1.f / l_b;
    size_t ra = (tok0 + w * 16 + (lane >> 2)) * HDn + hcol + (lane & 3) * 2;
#pragma unroll
    for (int nf = 0; nf < 16; nf++) {
        uint32_t hh, ll;
        split2h(oa[nf][0] * ia, oa[nf][1] * ia, hh, ll);
        *(uint32_t*)&Yh[ra + nf * 8] = hh;
        *(uint32_t*)&Yl[ra + nf * 8] = ll;
        split2h(oa[nf][2] * ib, oa[nf][3] * ib, hh, ll);
        *(uint32_t*)&Yh[ra + 8 * HDn + nf * 8] = hh;
        *(uint32_t*)&Yl[ra + 8 * HDn + nf * 8] = ll;
    }
}

// ---------------- launch (single stream, R9 ordering) ------------------------
extern "C" void kernel_launch(void* const* d_in, const int* in_sizes, int n_in,
                              void* d_out, int out_size) {
    const float* x       = (const float*)d_in[0];
    const float* xall    = (const float*)d_in[1];
    const int*   posx    = (const int*)d_in[2];
    const int*   posxall = (const int*)d_in[3];
    const void*  mask    = d_in[4];
    const float* Wq      = (const float*)d_in[5];
    const float* Wk      = (const float*)d_in[6];
    const float* Wv      = (const float*)d_in[7];
    const float* Wo      = (const float*)d_in[8];
    float* out = (float*)d_out;

    __half *xh, *xl, *ah, *al, *qh, *ql, *kh, *vh, *yh, *yl, *wq, *wk, *wv, *wo;
    int *sel, *nkp;
    cudaGetSymbolAddress((void**)&xh, g_xh);
    cudaGetSymbolAddress((void**)&xl, g_xl);
    cudaGetSymbolAddress((void**)&ah, g_ah);
    cudaGetSymbolAddress((void**)&al, g_al);
    cudaGetSymbolAddress((void**)&qh, g_qh);
    cudaGetSymbolAddress((void**)&ql, g_ql);
    cudaGetSymbolAddress((void**)&kh, g_kh);
    cudaGetSymbolAddress((void**)&vh, g_vh);
    cudaGetSymbolAddress((void**)&yh, g_yh);
    cudaGetSymbolAddress((void**)&yl, g_yl);
    cudaGetSymbolAddress((void**)&wq, g_wq);
    cudaGetSymbolAddress((void**)&wk, g_wk);
    cudaGetSymbolAddress((void**)&wv, g_wv);
    cudaGetSymbolAddress((void**)&wo, g_wo);
    cudaGetSymbolAddress((void**)&sel, g_sel);
    cudaGetSymbolAddress((void**)&nkp, g_nkeep);

    cudaFuncSetAttribute(bgemm_kernel<0>, cudaFuncAttributeMaxDynamicSharedMemorySize, GSMEM);
    cudaFuncSetAttribute(bgemm_kernel<1>, cudaFuncAttributeMaxDynamicSharedMemorySize, GSMEM);
    cudaFuncSetAttribute(bgemm_kernel<2>, cudaFuncAttributeMaxDynamicSharedMemorySize, GSMEM);
    cudaFuncSetAttribute(bgemm_kernel<3>, cudaFuncAttributeMaxDynamicSharedMemorySize, GSMEM);
    cudaFuncSetAttribute(attn_kernel, cudaFuncAttributeMaxDynamicSharedMemorySize, ATTN_SMEM);

    ropetab_kernel<<<(POSN * 64 + 255) / 256, 256>>>();
    sniff_kernel<<<1, 256>>>((const unsigned char*)mask);
    selbuild_kernel<<<Bb, 1024>>>(mask);

    const int NE4 = NTOK * En / 4;
    dim3 gs((NE4 + 255) / 256, 1, 2);
    splitH2x2_kernel<<<gs, 256>>>(x, xall, xh, xl, ah, al, NE4);
    dim3 gt(64, 64, 4), bt(32, 8);
    splitT4_kernel<<<gt, bt>>>(Wq, Wk, Wv, Wo, wq, wk, wv, wo);

    dim3 gg(HDn / 128, NTOK / 128);
    bgemm_kernel<1><<<gg, 256, GSMEM>>>(xh, xl, wq, nullptr, qh, ql,
                                        nullptr, posx, nullptr, NTOK, HDn, En);
    bgemm_kernel<2><<<gg, 256, GSMEM>>>(ah, al, wk, nullptr, kh, nullptr,
                                        sel, posxall, nkp, NTOK, HDn, En);
    bgemm_kernel<3><<<gg, 256, GSMEM>>>(ah, al, wv, nullptr, vh, nullptr,
                                        sel, nullptr, nkp, NTOK, HDn, En);

    dim3 ga(TQn / 64, Hn, Bb);
    attn_kernel<<<ga, 128, ATTN_SMEM>>>(qh, ql, kh, vh, yh, yl);

    dim3 go(En / 128, NTOK / 128);
    bgemm_kernel<0><<<go, 256, GSMEM>>>(yh, yl, wo, out, nullptr, nullptr,
                                        nullptr, nullptr, nullptr, NTOK, En, HDn);
}

// round 15
// speedup vs baseline: 1.4205x; 1.0025x over previous
#include <cuda_runtime.h>
#include <cuda_fp16.h>
#include <cuda_bf16.h>
#include <math.h>
#include <stdint.h>

#define Bb 4
#define TQn 2048
#define Tn 2048
#define En 2048
#define Hn 16
#define Dn 128
#define HDn 2048
#define NTOK 8192
#define POSN 4096

// ---------------- scratch ----------------------------------------------------
__device__ float g_cos[POSN * 64];
__device__ float g_sin[POSN * 64];
__device__ int   g_sel[NTOK];
__device__ int   g_nkeep[Bb];

__device__ __half g_xh[(size_t)NTOK * En];
__device__ __half g_xl[(size_t)NTOK * En];
__device__ __half g_ah[(size_t)NTOK * En];
__device__ __half g_al[(size_t)NTOK * En];
__device__ __half g_qh[(size_t)NTOK * HDn];
__device__ __half g_ql[(size_t)NTOK * HDn];
__device__ __half g_kh[(size_t)NTOK * HDn];
__device__ __half g_vh[(size_t)NTOK * HDn];
__device__ __half g_yh[(size_t)NTOK * HDn];
__device__ __half g_yl[(size_t)NTOK * HDn];
__device__ __half g_wq[(size_t)En * HDn];
__device__ __half g_wk[(size_t)En * HDn];
__device__ __half g_wv[(size_t)En * HDn];
__device__ __half g_wo[(size_t)En * HDn];

// ---------------- helpers ----------------------------------------------------
__device__ __forceinline__ float neginf() { return __int_as_float(0xff800000u); }

__device__ __forceinline__ uint32_t smem_u32(const void* p) {
    uint32_t a;
    asm("{ .reg .u64 t; cvta.to.shared.u64 t, %1; cvt.u32.u64 %0, t; }" : "=r"(a) : "l"(p));
    return a;
}
__device__ __forceinline__ void mma16816(float* d, const uint32_t* a, const uint32_t* b) {
    asm volatile("mma.sync.aligned.m16n8k16.row.col.f32.f16.f16.f32 "
        "{%0,%1,%2,%3}, {%4,%5,%6,%7}, {%8,%9}, {%0,%1,%2,%3};"
        : "+f"(d[0]), "+f"(d[1]), "+f"(d[2]), "+f"(d[3])
        : "r"(a[0]), "r"(a[1]), "r"(a[2]), "r"(a[3]), "r"(b[0]), "r"(b[1]));
}
__device__ __forceinline__ void ldm4(uint32_t* r, uint32_t a) {
    asm volatile("ldmatrix.sync.aligned.m8n8.x4.shared.b16 {%0,%1,%2,%3}, [%4];"
        : "=r"(r[0]), "=r"(r[1]), "=r"(r[2]), "=r"(r[3]) : "r"(a));
}
__device__ __forceinline__ void ldm4t(uint32_t* r, uint32_t a) {
    asm volatile("ldmatrix.sync.aligned.m8n8.x4.trans.shared.b16 {%0,%1,%2,%3}, [%4];"
        : "=r"(r[0]), "=r"(r[1]), "=r"(r[2]), "=r"(r[3]) : "r"(a));
}
__device__ __forceinline__ void cpa16(uint32_t d, const void* s) {
    asm volatile("cp.async.cg.shared.global [%0], [%1], 16;" :: "r"(d), "l"(s));
}
#define CP_COMMIT() asm volatile("cp.async.commit_group;" ::: "memory")
#define CP_WAIT1()  asm volatile("cp.async.wait_group 1;" ::: "memory")

__device__ __forceinline__ void split2h(float a, float b, uint32_t& hi, uint32_t& lo) {
    __half2 h = __floats2half2_rn(a, b);
    hi = *(uint32_t*)&h;
    __half2 l = __floats2half2_rn(a - __low2float(h), b - __high2float(h));
    lo = *(uint32_t*)&l;
}

__device__ __forceinline__ bool mask_at(const void* m, int i, int k) {
    if (k == 0) return ((const unsigned char*)m)[i] != 0;
    if (k == 1) return ((const int*)m)[i] != 0;
    if (k == 2) return ((const float*)m)[i] != 0.0f;
    return __bfloat162float(((const __nv_bfloat16*)m)[i]) != 0.0f;
}

// ---------------- small kernels ---------------------------------------------
__global__ void ropetab_kernel() {
    int t = blockIdx.x * 256 + threadIdx.x;
    if (t >= POSN * 64) return;
    int j = t & 63, p = t >> 6;
    double inv = 1.0 / pow(10000.0, (double)(2 * j) / 128.0);
    float invf = (float)inv;
    float ang = (float)p * invf;
    g_cos[t] = (float)cos((double)ang);
    g_sin[t] = (float)sin((double)ang);
}

// fused dtype-sniff + per-batch compaction (each block redoes the cheap sniff)
__global__ void selbuild_kernel(const void* m) {
    __shared__ int sc[1024];
    __shared__ int stot;
    __shared__ int f[3];
    int b = blockIdx.x, tid = threadIdx.x;
    if (tid < 3) f[tid] = 0;
    __syncthreads();
    {
        const unsigned char* mb = (const unsigned char*)m;
        int a = 0, bb = 0, c = 0;
        for (int i = tid; i < Bb * Tn; i += 1024) {
            unsigned v = mb[i];
            if (v > 1) a = 1;
            if (v != 0 && (i & 3)) bb = 1;
            if (v != 0 && ((i & 3) < 2)) c = 1;
        }
        if (a) atomicOr(&f[0], 1);
        if (bb) atomicOr(&f[1], 1);
        if (c) atomicOr(&f[2], 1);
    }
    __syncthreads();
    int kind = (!f[0]) ? (f[1] ? 0 : 1) : (f[2] ? 3 : 2);

    int i0 = tid * 2, i1 = i0 + 1;
    int k0 = mask_at(m, b * Tn + i0, kind) ? 0 : 1;
    int k1 = mask_at(m, b * Tn + i1, kind) ? 0 : 1;
    int part = k0 + k1;
    sc[tid] = part;
    __syncthreads();
    for (int off = 1; off < 1024; off <<= 1) {
        int v = (tid >= off) ? sc[tid - off] : 0;
        __syncthreads();
        sc[tid] += v;
        __syncthreads();
    }
    int base = sc[tid] - part;
    if (k0) g_sel[b * Tn + base] = b * Tn + i0;
    if (k1) g_sel[b * Tn + base + k0] = b * Tn + i1;
    if (tid == 1023) { g_nkeep[b] = sc[1023]; stot = sc[1023]; }
    __syncthreads();
    for (int i = stot + tid; i < Tn; i += 1024) g_sel[b * Tn + i] = b * Tn;
}

// fused: z=0 splits x -> xh/xl, z=1 splits xall -> ah/al
__global__ void splitH2x2_kernel(const float* __restrict__ x0,
                                 const float* __restrict__ x1,
                                 __half* __restrict__ h0, __half* __restrict__ l0,
                                 __half* __restrict__ h1, __half* __restrict__ l1,
                                 int n4) {
    int i = blockIdx.x * 256 + threadIdx.x;
    if (i >= n4) return;
    const float* in = blockIdx.z ? x1 : x0;
    __half* hi = blockIdx.z ? h1 : h0;
    __half* lo = blockIdx.z ? l1 : l0;
    float4 v = ((const float4*)in)[i];
    uint32_t a0, b0, a1, b1;
    split2h(v.x, v.y, a0, b0);
    split2h(v.z, v.w, a1, b1);
    ((uint32_t*)hi)[i * 2]     = a0;
    ((uint32_t*)hi)[i * 2 + 1] = a1;
    ((uint32_t*)lo)[i * 2]     = b0;
    ((uint32_t*)lo)[i * 2 + 1] = b1;
}

// fused: all four weight transposes in one launch (z selects weight)
__global__ void splitT4_kernel(const float* __restrict__ Wq, const float* __restrict__ Wk,
                               const float* __restrict__ Wv, const float* __restrict__ Wo,
                               __half* __restrict__ oq, __half* __restrict__ ok,
                               __half* __restrict__ ov, __half* __restrict__ oo) {
    __shared__ float t[32][33];
    int z = blockIdx.z;
    const float* W = (z == 0) ? Wq : (z == 1) ? Wk : (z == 2) ? Wv : Wo;
    __half* out    = (z == 0) ? oq : (z == 1) ? ok : (z == 2) ? ov : oo;
    int perm = (z < 2) ? 1 : 0;
    int n0 = blockIdx.x * 32, k0 = blockIdx.y * 32;
    for (int r = threadIdx.y; r < 32; r += 8)
        t[r][threadIdx.x] = W[(size_t)(k0 + r) * 2048 + n0 + threadIdx.x];
    __syncthreads();
    for (int r = threadIdx.y; r < 32; r += 8) {
        int n = n0 + r;
        int rr = n & 127;
        int nout = perm ? ((n & ~127) | (rr < 64 ? (rr * 2) : ((rr - 64) * 2 + 1))) : n;
        out[(size_t)nout * 2048 + k0 + threadIdx.x] = __float2half(t[threadIdx.x][r]);
    }
}

// ---------------- HMMA fp16x2 GEMM, K-tile 64, 1 sync/iter -------------------
#define GROW 144                 // 128B data + 16B pad (9 x 16B, coprime with 8)
#define GTILE (128 * GROW)       // 18432
#define GST   (3 * GTILE)        // 55296 per stage (Ahi, Alo, B)
#define GSMEM (3 * GST)          // 165888

template<int MODE>
__global__ __launch_bounds__(256, 1) void bgemm_kernel(
    const __half* __restrict__ Ahi, const __half* __restrict__ Alo,
    const __half* __restrict__ Bh, float* __restrict__ Cf,
    __half* __restrict__ Oh, __half* __restrict__ Ol,
    const int* __restrict__ Asel, const int* __restrict__ pos,
    const int* __restrict__ nkp, int M, int N, int K) {
    extern __shared__ __align__(128) char gsm[];
    uint32_t sb = smem_u32(gsm);
    int tid = threadIdx.x, lane = tid & 31, wid = tid >> 5;
    int wm = wid & 1, wn = wid >> 1;
    size_t bm = (size_t)blockIdx.y * 128, bn = (size_t)blockIdx.x * 128;

    if (nkp != nullptr) {
        if ((int)(bm & (Tn - 1)) >= nkp[bm >> 11]) return;
    }

    const __half* srcb[12];
    uint32_t dstb[12];
#pragma unroll
    for (int i = 0; i < 12; i++) {
        int id = tid + i * 256, tile = id >> 10, w = id & 1023, row = w >> 3, c = w & 7;
        const __half* base = (tile == 0) ? Ahi : (tile == 1) ? Alo : Bh;
        size_t grow;
        if (tile < 2) grow = Asel ? (size_t)Asel[bm + row] : (bm + row);
        else          grow = bn + row;
        srcb[i] = base + grow * (size_t)K + c * 8;
        dstb[i] = sb + tile * GTILE + row * GROW + c * 16;
    }

    float acc[4][4][4];
#pragma unroll
    for (int a = 0; a < 4; a++)
#pragma unroll
        for (int b = 0; b < 4; b++)
#pragma unroll
            for (int c = 0; c < 4; c++) acc[a][b][c] = 0.f;

    const int NT = K / 64;
#pragma unroll
    for (int s = 0; s < 2; s++) {
#pragma unroll
        for (int i = 0; i < 12; i++) cpa16(dstb[i] + s * GST, srcb[i] + s * 64);
        CP_COMMIT();
    }

    for (int kt = 0; kt < NT; kt++) {
        CP_WAIT1();
        __syncthreads();   // stage kt landed AND all threads done computing kt-1
        if (kt + 2 < NT) {
            uint32_t so = ((kt + 2) % 3) * GST;
#pragma unroll
            for (int i = 0; i < 12; i++) cpa16(dstb[i] + so, srcb[i] + (kt + 2) * 64);
        }
        CP_COMMIT();

        uint32_t st = sb + (kt % 3) * GST;
        uint32_t arow = st + (wm * 64 + (lane & 15)) * GROW + ((lane >> 4) << 4);
        uint32_t brow = st + 2 * GTILE +
                        (wn * 32 + (lane & 7) + ((lane >> 4) << 3)) * GROW +
                        (((lane >> 3) & 1) << 4);
#pragma unroll
        for (int kf = 0; kf < 4; kf++) {
            uint32_t ah[4][4], al[4][4];
#pragma unroll
            for (int mi = 0; mi < 4; mi++) {
                ldm4(ah[mi], arow + mi * 16 * GROW + kf * 32);
                ldm4(al[mi], arow + GTILE + mi * 16 * GROW + kf * 32);
            }
#pragma unroll
            for (int njp = 0; njp < 2; njp++) {
                uint32_t bh[4];
                ldm4(bh, brow + njp * 16 * GROW + kf * 32);
#pragma unroll
                for (int mi = 0; mi < 4; mi++) {
                    mma16816(acc[mi][2 * njp],     ah[mi], bh);
                    mma16816(acc[mi][2 * njp],     al[mi], bh);
                    mma16816(acc[mi][2 * njp + 1], ah[mi], bh + 2);
                    mma16816(acc[mi][2 * njp + 1], al[mi], bh + 2);
                }
            }
        }
        // no bottom sync: next iteration's top sync orders buffer reuse
    }

#pragma unroll
    for (int mi = 0; mi < 4; mi++) {
        size_t r0 = bm + wm * 64 + mi * 16 + (lane >> 2);
        size_t r1 = r0 + 8;
        int p0 = 0, p1 = 0;
        if (MODE == 1 || MODE == 2) {
            p0 = pos[Asel ? Asel[r0] : (int)r0];
            p1 = pos[Asel ? Asel[r1] : (int)r1];
        }
#pragma unroll
        for (int nj = 0; nj < 4; nj++) {
            size_t cc = bn + wn * 32 + nj * 8 + (lane & 3) * 2;
            float a0 = acc[mi][nj][0], b0 = acc[mi][nj][1];
            float a1 = acc[mi][nj][2], b1 = acc[mi][nj][3];
            if (MODE == 0) {
                *(float2*)&Cf[r0 * N + cc] = make_float2(a0, b0);
                *(float2*)&Cf[r1 * N + cc] = make_float2(a1, b1);
            } else if (MODE == 3) {
                *(__half2*)&Oh[r0 * N + cc] = __floats2half2_rn(a0, b0);
                *(__half2*)&Oh[r1 * N + cc] = __floats2half2_rn(a1, b1);
            } else {
                int j = ((int)cc & 127) >> 1;
                float c0 = g_cos[p0 * 64 + j], s0 = g_sin[p0 * 64 + j];
                float c1 = g_cos[p1 * 64 + j], s1 = g_sin[p1 * 64 + j];
                float e0 = a0 * c0 - b0 * s0, o0 = b0 * c0 + a0 * s0;
                float e1 = a1 * c1 - b1 * s1, o1 = b1 * c1 + a1 * s1;
                if (MODE == 1) {
                    uint32_t h, l;
                    split2h(e0, o0, h, l);
                    *(uint32_t*)&Oh[r0 * N + cc] = h;
                    *(uint32_t*)&Ol[r0 * N + cc] = l;
                    split2h(e1, o1, h, l);
                    *(uint32_t*)&Oh[r1 * N + cc] = h;
                    *(uint32_t*)&Ol[r1 * N + cc] = l;
                } else {
                    *(__half2*)&Oh[r0 * N + cc] = __floats2half2_rn(e0, o0);
                    *(__half2*)&Oh[r1 * N + cc] = __floats2half2_rn(e1, o1);
                }
            }
        }
    }
}

// ---------------- HMMA flash attention: 64q x 64k, 4 warps -------------------
#define ATQ 272
#define S_QH 0
#define S_QL 17408
#define S_K  34816
#define S_V  52224
#define ATTN_SMEM 69632

__global__ __launch_bounds__(128) void attn_kernel(
    const __half* __restrict__ Qh, const __half* __restrict__ Ql,
    const __half* __restrict__ Kh, const __half* __restrict__ Vh,
    __half* __restrict__ Yh, __half* __restrict__ Yl) {
    extern __shared__ __align__(128) char ash[];
    uint32_t sb = smem_u32(ash);
    int tid = threadIdx.x, lane = tid & 31, w = tid >> 5;
    int qb = blockIdx.x * 64, h = blockIdx.y, b = blockIdx.z;
    size_t tok0 = (size_t)b * TQn + qb;
    size_t ktok0 = (size_t)b * Tn;
    int hcol = h * 128;
    const float NI = neginf();
    const float scale = 0.08838834764831845f;
    const int nk = g_nkeep[b];
    const int nt = (nk + 63) >> 6;

#pragma unroll
    for (int i = 0; i < 16; i++) {
        int id = tid + i * 128;
        int buf = id >> 10, ww = id & 1023, row = ww >> 4, c = ww & 15;
        const __half* src = (buf ? Ql : Qh) + (tok0 + row) * HDn + hcol + c * 8;
        *(uint4*)(ash + (buf ? S_QL : S_QH) + row * ATQ + c * 16) = *(const uint4*)src;
    }
    __syncthreads();

    uint32_t qhf[8][4], qlf[8][4];
    {
        uint32_t abase = sb + (w * 16 + (lane & 15)) * ATQ + ((lane >> 4) << 4);
#pragma unroll
        for (int kf = 0; kf < 8; kf++) {
            ldm4(qhf[kf], abase + kf * 32);
            ldm4(qlf[kf], abase + S_QL + kf * 32);
        }
    }

    float oa[16][4];
#pragma unroll
    for (int i = 0; i < 16; i++)
#pragma unroll
        for (int j = 0; j < 4; j++) oa[i][j] = 0.f;
    float m_a = NI, m_b = NI, l_a = 0.f, l_b = 0.f;

    int crow = tid >> 4, ccol = tid & 15;
    uint32_t kdst = sb + S_K + crow * ATQ + ccol * 16;
    uint32_t vdst = sb + S_V + crow * ATQ + ccol * 16;
    const __half* ksrc0 = Kh + (ktok0 + crow) * HDn + hcol + ccol * 8;
    const __half* vsrc0 = Vh + (ktok0 + crow) * HDn + hcol + ccol * 8;

#define ISSUE_K(kt) do { \
    const __half* _s = ksrc0 + (size_t)(kt) * 64 * HDn; \
    _Pragma("unroll") for (int _i = 0; _i < 8; _i++) \
        cpa16(kdst + _i * 8 * ATQ, _s + (size_t)_i * 8 * HDn); \
} while (0)
#define ISSUE_V(kt) do { \
    const __half* _s = vsrc0 + (size_t)(kt) * 64 * HDn; \
    _Pragma("unroll") for (int _i = 0; _i < 8; _i++) \
        cpa16(vdst + _i * 8 * ATQ, _s + (size_t)_i * 8 * HDn); \
} while (0)

    ISSUE_K(0); CP_COMMIT();
    ISSUE_V(0); CP_COMMIT();

    for (int kt = 0; kt < nt; kt++) {
        CP_WAIT1();
        __syncthreads();

        // S = Q K^T
        float sc[8][4];
#pragma unroll
        for (int i = 0; i < 8; i++)
#pragma unroll
            for (int j = 0; j < 4; j++) sc[i][j] = 0.f;
        {
            uint32_t bbase = sb + S_K +
                ((lane & 7) + ((lane >> 4) << 3)) * ATQ + (((lane >> 3) & 1) << 4);
#pragma unroll
            for (int kf = 0; kf < 8; kf++) {
#pragma unroll
                for (int njp = 0; njp < 4; njp++) {
                    uint32_t kh4[4];
                    ldm4(kh4, bbase + njp * 16 * ATQ + kf * 32);
                    mma16816(sc[2 * njp],     qhf[kf], kh4);
                    mma16816(sc[2 * njp],     qlf[kf], kh4);
                    mma16816(sc[2 * njp + 1], qhf[kf], kh4 + 2);
                    mma16816(sc[2 * njp + 1], qlf[kf], kh4 + 2);
                }
            }
        }
        __syncthreads();
        ISSUE_K((kt + 1) & 31); CP_COMMIT();

        // validity from compaction (register compare)
        float ta = NI, tb = NI;
        bool v0[8], v1[8];
#pragma unroll
        for (int nf = 0; nf < 8; nf++) {
            int key0 = kt * 64 + nf * 8 + ((lane & 3) << 1);
            v0[nf] = key0 < nk;
            v1[nf] = key0 + 1 < nk;
#pragma unroll
            for (int j = 0; j < 4; j++) sc[nf][j] *= scale;
            if (v0[nf]) { ta = fmaxf(ta, sc[nf][0]); tb = fmaxf(tb, sc[nf][2]); }
            if (v1[nf]) { ta = fmaxf(ta, sc[nf][1]); tb = fmaxf(tb, sc[nf][3]); }
        }
        ta = fmaxf(ta, __shfl_xor_sync(0xffffffffu, ta, 1));
        ta = fmaxf(ta, __shfl_xor_sync(0xffffffffu, ta, 2));
        tb = fmaxf(tb, __shfl_xor_sync(0xffffffffu, tb, 1));
        tb = fmaxf(tb, __shfl_xor_sync(0xffffffffu, tb, 2));
        float mna = fmaxf(m_a, ta), mnb = fmaxf(m_b, tb);
        float alpha_a = (m_a > NI) ? __expf(m_a - mna) : 1.f;
        float alpha_b = (m_b > NI) ? __expf(m_b - mnb) : 1.f;
        m_a = mna; m_b = mnb;

        float sa = 0.f, sbm = 0.f;
#pragma unroll
        for (int nf = 0; nf < 8; nf++) {
            float p0 = (!v0[nf] || m_a == NI) ? 0.f : __expf(sc[nf][0] - m_a);
            float p1 = (!v1[nf] || m_a == NI) ? 0.f : __expf(sc[nf][1] - m_a);
            float p2 = (!v0[nf] || m_b == NI) ? 0.f : __expf(sc[nf][2] - m_b);
            float p3 = (!v1[nf] || m_b == NI) ? 0.f : __expf(sc[nf][3] - m_b);
            sc[nf][0] = p0; sc[nf][1] = p1; sc[nf][2] = p2; sc[nf][3] = p3;
            sa += p0 + p1; sbm += p2 + p3;
        }
        sa  += __shfl_xor_sync(0xffffffffu, sa, 1);
        sa  += __shfl_xor_sync(0xffffffffu, sa, 2);
        sbm += __shfl_xor_sync(0xffffffffu, sbm, 1);
        sbm += __shfl_xor_sync(0xffffffffu, sbm, 2);
        l_a = l_a * alpha_a + sa;
        l_b = l_b * alpha_b + sbm;
#pragma unroll
        for (int nf = 0; nf < 16; nf++) {
            oa[nf][0] *= alpha_a; oa[nf][1] *= alpha_a;
            oa[nf][2] *= alpha_b; oa[nf][3] *= alpha_b;
        }

        uint32_t ph[4][4], pl[4][4];
#pragma unroll
        for (int t = 0; t < 4; t++) {
            split2h(sc[2 * t][0],     sc[2 * t][1],     ph[t][0], pl[t][0]);
            split2h(sc[2 * t][2],     sc[2 * t][3],     ph[t][1], pl[t][1]);
            split2h(sc[2 * t + 1][0], sc[2 * t + 1][1], ph[t][2], pl[t][2]);
            split2h(sc[2 * t + 1][2], sc[2 * t + 1][3], ph[t][3], pl[t][3]);
        }

        CP_WAIT1();
        __syncthreads();

        // O += P V
        {
            uint32_t vbase = sb + S_V +
                ((lane & 7) + (((lane >> 3) & 1) << 3)) * ATQ + ((lane >> 4) << 4);
#pragma unroll
            for (int t = 0; t < 4; t++) {
#pragma unroll
                for (int njp = 0; njp < 8; njp++) {
                    uint32_t vh4[4];
                    ldm4t(vh4, vbase + t * 16 * ATQ + njp * 32);
                    int n0 = njp * 2, n1 = n0 + 1;
                    mma16816(oa[n0], ph[t], vh4);
                    mma16816(oa[n0], pl[t], vh4);
                    mma16816(oa[n1], ph[t], vh4 + 2);
                    mma16816(oa[n1], pl[t], vh4 + 2);
                }
            }
        }
        __syncthreads();
        ISSUE_V((kt + 1) & 31); CP_COMMIT();
    }

    float ia = 1.f / l_a, ib = 1.f / l_b;
    size_t ra = (tok0 + w * 16 + (lane >> 2)) * HDn + hcol + (lane & 3) * 2;
#pragma unroll
    for (int nf = 0; nf < 16; nf++) {
        uint32_t hh, ll;
        split2h(oa[nf][0] * ia, oa[nf][1] * ia, hh, ll);
        *(uint32_t*)&Yh[ra + nf * 8] = hh;
        *(uint32_t*)&Yl[ra + nf * 8] = ll;
        split2h(oa[nf][2] * ib, oa[nf][3] * ib, hh, ll);
        *(uint32_t*)&Yh[ra + 8 * HDn + nf * 8] = hh;
        *(uint32_t*)&Yl[ra + 8 * HDn + nf * 8] = ll;
    }
}

// ---------------- launch (single stream) -------------------------------------
extern "C" void kernel_launch(void* const* d_in, const int* in_sizes, int n_in,
                              void* d_out, int out_size) {
    const float* x       = (const float*)d_in[0];
    const float* xall    = (const float*)d_in[1];
    const int*   posx    = (const int*)d_in[2];
    const int*   posxall = (const int*)d_in[3];
    const void*  mask    = d_in[4];
    const float* Wq      = (const float*)d_in[5];
    const float* Wk      = (const float*)d_in[6];
    const float* Wv      = (const float*)d_in[7];
    const float* Wo      = (const float*)d_in[8];
    float* out = (float*)d_out;

    __half *xh, *xl, *ah, *al, *qh, *ql, *kh, *vh, *yh, *yl, *wq, *wk, *wv, *wo;
    int *sel, *nkp;
    cudaGetSymbolAddress((void**)&xh, g_xh);
    cudaGetSymbolAddress((void**)&xl, g_xl);
    cudaGetSymbolAddress((void**)&ah, g_ah);
    cudaGetSymbolAddress((void**)&al, g_al);
    cudaGetSymbolAddress((void**)&qh, g_qh);
    cudaGetSymbolAddress((void**)&ql, g_ql);
    cudaGetSymbolAddress((void**)&kh, g_kh);
    cudaGetSymbolAddress((void**)&vh, g_vh);
    cudaGetSymbolAddress((void**)&yh, g_yh);
    cudaGetSymbolAddress((void**)&yl, g_yl);
    cudaGetSymbolAddress((void**)&wq, g_wq);
    cudaGetSymbolAddress((void**)&wk, g_wk);
    cudaGetSymbolAddress((void**)&wv, g_wv);
    cudaGetSymbolAddress((void**)&wo, g_wo);
    cudaGetSymbolAddress((void**)&sel, g_sel);
    cudaGetSymbolAddress((void**)&nkp, g_nkeep);

    cudaFuncSetAttribute(bgemm_kernel<0>, cudaFuncAttributeMaxDynamicSharedMemorySize, GSMEM);
    cudaFuncSetAttribute(bgemm_kernel<1>, cudaFuncAttributeMaxDynamicSharedMemorySize, GSMEM);
    cudaFuncSetAttribute(bgemm_kernel<2>, cudaFuncAttributeMaxDynamicSharedMemorySize, GSMEM);
    cudaFuncSetAttribute(bgemm_kernel<3>, cudaFuncAttributeMaxDynamicSharedMemorySize, GSMEM);
    cudaFuncSetAttribute(attn_kernel, cudaFuncAttributeMaxDynamicSharedMemorySize, ATTN_SMEM);

    ropetab_kernel<<<(POSN * 64 + 255) / 256, 256>>>();
    selbuild_kernel<<<Bb, 1024>>>(mask);

    const int NE4 = NTOK * En / 4;
    dim3 gs((NE4 + 255) / 256, 1, 2);
    splitH2x2_kernel<<<gs, 256>>>(x, xall, xh, xl, ah, al, NE4);
    dim3 gt(64, 64, 4), bt(32, 8);
    splitT4_kernel<<<gt, bt>>>(Wq, Wk, Wv, Wo, wq, wk, wv, wo);

    dim3 gg(HDn / 128, NTOK / 128);
    bgemm_kernel<1><<<gg, 256, GSMEM>>>(xh, xl, wq, nullptr, qh, ql,
                                        nullptr, posx, nullptr, NTOK, HDn, En);
    bgemm_kernel<2><<<gg, 256, GSMEM>>>(ah, al, wk, nullptr, kh, nullptr,
                                        sel, posxall, nkp, NTOK, HDn, En);
    bgemm_kernel<3><<<gg, 256, GSMEM>>>(ah, al, wv, nullptr, vh, nullptr,
                                        sel, nullptr, nkp, NTOK, HDn, En);

    dim3 ga(TQn / 64, Hn, Bb);
    attn_kernel<<<ga, 128, ATTN_SMEM>>>(qh, ql, kh, vh, yh, yl);

    dim3 go(En / 128, NTOK / 128);
    bgemm_kernel<0><<<go, 256, GSMEM>>>(yh, yl, wo, out, nullptr, nullptr,
                                        nullptr, nullptr, nullptr, NTOK, En, HDn);
}

// round 17
// speedup vs baseline: 1.4500x; 1.0208x over previous
#include <cuda_runtime.h>
#include <cuda_fp16.h>
#include <cuda_bf16.h>
#include <math.h>
#include <stdint.h>

#define Bb 4
#define TQn 2048
#define Tn 2048
#define En 2048
#define Hn 16
#define Dn 128
#define HDn 2048
#define NTOK 8192
#define POSN 4096

// ---------------- scratch ----------------------------------------------------
__device__ float g_cos[POSN * 64];
__device__ float g_sin[POSN * 64];
__device__ int   g_sel[NTOK];
__device__ int   g_nkeep[Bb];

__device__ __half g_xh[(size_t)NTOK * En];
__device__ __half g_xl[(size_t)NTOK * En];
__device__ __half g_ah[(size_t)NTOK * En];
__device__ __half g_al[(size_t)NTOK * En];
__device__ __half g_qh[(size_t)NTOK * HDn];
__device__ __half g_ql[(size_t)NTOK * HDn];
__device__ __half g_kh[(size_t)NTOK * HDn];
__device__ __half g_vh[(size_t)NTOK * HDn];
__device__ __half g_yh[(size_t)NTOK * HDn];
__device__ __half g_yl[(size_t)NTOK * HDn];
__device__ __half g_wq[(size_t)En * HDn];
__device__ __half g_wk[(size_t)En * HDn];
__device__ __half g_wv[(size_t)En * HDn];
__device__ __half g_wo[(size_t)En * HDn];

// ---------------- helpers ----------------------------------------------------
__device__ __forceinline__ float neginf() { return __int_as_float(0xff800000u); }

__device__ __forceinline__ uint32_t smem_u32(const void* p) {
    uint32_t a;
    asm("{ .reg .u64 t; cvta.to.shared.u64 t, %1; cvt.u32.u64 %0, t; }" : "=r"(a) : "l"(p));
    return a;
}
__device__ __forceinline__ void mma16816(float* d, const uint32_t* a, const uint32_t* b) {
    asm volatile("mma.sync.aligned.m16n8k16.row.col.f32.f16.f16.f32 "
        "{%0,%1,%2,%3}, {%4,%5,%6,%7}, {%8,%9}, {%0,%1,%2,%3};"
        : "+f"(d[0]), "+f"(d[1]), "+f"(d[2]), "+f"(d[3])
        : "r"(a[0]), "r"(a[1]), "r"(a[2]), "r"(a[3]), "r"(b[0]), "r"(b[1]));
}
__device__ __forceinline__ void ldm4(uint32_t* r, uint32_t a) {
    asm volatile("ldmatrix.sync.aligned.m8n8.x4.shared.b16 {%0,%1,%2,%3}, [%4];"
        : "=r"(r[0]), "=r"(r[1]), "=r"(r[2]), "=r"(r[3]) : "r"(a));
}
__device__ __forceinline__ void ldm4t(uint32_t* r, uint32_t a) {
    asm volatile("ldmatrix.sync.aligned.m8n8.x4.trans.shared.b16 {%0,%1,%2,%3}, [%4];"
        : "=r"(r[0]), "=r"(r[1]), "=r"(r[2]), "=r"(r[3]) : "r"(a));
}
__device__ __forceinline__ void cpa16(uint32_t d, const void* s) {
    asm volatile("cp.async.cg.shared.global [%0], [%1], 16;" :: "r"(d), "l"(s));
}
#define CP_COMMIT() asm volatile("cp.async.commit_group;" ::: "memory")
#define CP_WAIT1()  asm volatile("cp.async.wait_group 1;" ::: "memory")

__device__ __forceinline__ void split2h(float a, float b, uint32_t& hi, uint32_t& lo) {
    __half2 h = __floats2half2_rn(a, b);
    hi = *(uint32_t*)&h;
    __half2 l = __floats2half2_rn(a - __low2float(h), b - __high2float(h));
    lo = *(uint32_t*)&l;
}

__device__ __forceinline__ bool mask_at(const void* m, int i, int k) {
    if (k == 0) return ((const unsigned char*)m)[i] != 0;
    if (k == 1) return ((const int*)m)[i] != 0;
    if (k == 2) return ((const float*)m)[i] != 0.0f;
    return __bfloat162float(((const __nv_bfloat16*)m)[i]) != 0.0f;
}

// ---------------- small kernels ---------------------------------------------
__global__ void ropetab_kernel() {
    int t = blockIdx.x * 256 + threadIdx.x;
    if (t >= POSN * 64) return;
    int j = t & 63, p = t >> 6;
    double inv = 1.0 / pow(10000.0, (double)(2 * j) / 128.0);
    float invf = (float)inv;
    float ang = (float)p * invf;
    g_cos[t] = (float)cos((double)ang);
    g_sin[t] = (float)sin((double)ang);
}

// fused dtype-sniff + per-batch compaction
__global__ void selbuild_kernel(const void* m) {
    __shared__ int sc[1024];
    __shared__ int stot;
    __shared__ int f[3];
    int b = blockIdx.x, tid = threadIdx.x;
    if (tid < 3) f[tid] = 0;
    __syncthreads();
    {
        const unsigned char* mb = (const unsigned char*)m;
        int a = 0, bb = 0, c = 0;
        for (int i = tid; i < Bb * Tn; i += 1024) {
            unsigned v = mb[i];
            if (v > 1) a = 1;
            if (v != 0 && (i & 3)) bb = 1;
            if (v != 0 && ((i & 3) < 2)) c = 1;
        }
        if (a) atomicOr(&f[0], 1);
        if (bb) atomicOr(&f[1], 1);
        if (c) atomicOr(&f[2], 1);
    }
    __syncthreads();
    int kind = (!f[0]) ? (f[1] ? 0 : 1) : (f[2] ? 3 : 2);

    int i0 = tid * 2, i1 = i0 + 1;
    int k0 = mask_at(m, b * Tn + i0, kind) ? 0 : 1;
    int k1 = mask_at(m, b * Tn + i1, kind) ? 0 : 1;
    int part = k0 + k1;
    sc[tid] = part;
    __syncthreads();
    for (int off = 1; off < 1024; off <<= 1) {
        int v = (tid >= off) ? sc[tid - off] : 0;
        __syncthreads();
        sc[tid] += v;
        __syncthreads();
    }
    int base = sc[tid] - part;
    if (k0) g_sel[b * Tn + base] = b * Tn + i0;
    if (k1) g_sel[b * Tn + base + k0] = b * Tn + i1;
    if (tid == 1023) { g_nkeep[b] = sc[1023]; stot = sc[1023]; }
    __syncthreads();
    for (int i = stot + tid; i < Tn; i += 1024) g_sel[b * Tn + i] = b * Tn;
}

// fused activation split, 2 float4 per thread (ILP)
__global__ void splitH2x2_kernel(const float* __restrict__ x0,
                                 const float* __restrict__ x1,
                                 __half* __restrict__ h0, __half* __restrict__ l0,
                                 __half* __restrict__ h1, __half* __restrict__ l1,
                                 int n4) {
    int i = (blockIdx.x * 256 + threadIdx.x) * 2;
    const float* in = blockIdx.z ? x1 : x0;
    __half* hi = blockIdx.z ? h1 : h0;
    __half* lo = blockIdx.z ? l1 : l0;
#pragma unroll
    for (int u = 0; u < 2; u++) {
        int idx = i + u;
        if (idx >= n4) break;
        float4 v = ((const float4*)in)[idx];
        uint32_t a0, b0, a1, b1;
        split2h(v.x, v.y, a0, b0);
        split2h(v.z, v.w, a1, b1);
        ((uint32_t*)hi)[idx * 2]     = a0;
        ((uint32_t*)hi)[idx * 2 + 1] = a1;
        ((uint32_t*)lo)[idx * 2]     = b0;
        ((uint32_t*)lo)[idx * 2 + 1] = b1;
    }
}

// fused weight transpose, vectorized half2 stores: 64k x 32n tiles
__global__ void splitT4_kernel(const float* __restrict__ Wq, const float* __restrict__ Wk,
                               const float* __restrict__ Wv, const float* __restrict__ Wo,
                               __half* __restrict__ oq, __half* __restrict__ ok,
                               __half* __restrict__ ov, __half* __restrict__ oo) {
    __shared__ float t[64][33];
    int z = blockIdx.z;
    const float* W = (z == 0) ? Wq : (z == 1) ? Wk : (z == 2) ? Wv : Wo;
    __half* out    = (z == 0) ? oq : (z == 1) ? ok : (z == 2) ? ov : oo;
    int perm = (z < 2) ? 1 : 0;
    int n0 = blockIdx.x * 32, k0 = blockIdx.y * 64;
    for (int r = threadIdx.y; r < 64; r += 8)
        t[r][threadIdx.x] = W[(size_t)(k0 + r) * 2048 + n0 + threadIdx.x];
    __syncthreads();
    for (int r = threadIdx.y; r < 32; r += 8) {
        int n = n0 + r;
        int rr = n & 127;
        int nout = perm ? ((n & ~127) | (rr < 64 ? (rr * 2) : ((rr - 64) * 2 + 1))) : n;
        __half2 v = __floats2half2_rn(t[2 * threadIdx.x][r], t[2 * threadIdx.x + 1][r]);
        *(__half2*)&out[(size_t)nout * 2048 + k0 + 2 * threadIdx.x] = v;
    }
}

// ---------------- HMMA fp16x2 GEMM, K-tile 64, 1 sync/iter -------------------
#define GROW 144
#define GTILE (128 * GROW)
#define GST   (3 * GTILE)
#define GSMEM (3 * GST)

template<int MODE>
__global__ __launch_bounds__(256, 1) void bgemm_kernel(
    const __half* __restrict__ Ahi, const __half* __restrict__ Alo,
    const __half* __restrict__ Bh, float* __restrict__ Cf,
    __half* __restrict__ Oh, __half* __restrict__ Ol,
    const int* __restrict__ Asel, const int* __restrict__ pos,
    const int* __restrict__ nkp, int M, int N, int K) {
    extern __shared__ __align__(128) char gsm[];
    uint32_t sb = smem_u32(gsm);
    int tid = threadIdx.x, lane = tid & 31, wid = tid >> 5;
    int wm = wid & 1, wn = wid >> 1;
    size_t bm = (size_t)blockIdx.y * 128, bn = (size_t)blockIdx.x * 128;

    if (nkp != nullptr) {
        if ((int)(bm & (Tn - 1)) >= nkp[bm >> 11]) return;
    }

    const __half* srcb[12];
    uint32_t dstb[12];
#pragma unroll
    for (int i = 0; i < 12; i++) {
        int id = tid + i * 256, tile = id >> 10, w = id & 1023, row = w >> 3, c = w & 7;
        const __half* base = (tile == 0) ? Ahi : (tile == 1) ? Alo : Bh;
        size_t grow;
        if (tile < 2) grow = Asel ? (size_t)Asel[bm + row] : (bm + row);
        else          grow = bn + row;
        srcb[i] = base + grow * (size_t)K + c * 8;
        dstb[i] = sb + tile * GTILE + row * GROW + c * 16;
    }

    float acc[4][4][4];
#pragma unroll
    for (int a = 0; a < 4; a++)
#pragma unroll
        for (int b = 0; b < 4; b++)
#pragma unroll
            for (int c = 0; c < 4; c++) acc[a][b][c] = 0.f;

    const int NT = K / 64;
#pragma unroll
    for (int s = 0; s < 2; s++) {
#pragma unroll
        for (int i = 0; i < 12; i++) cpa16(dstb[i] + s * GST, srcb[i] + s * 64);
        CP_COMMIT();
    }

    for (int kt = 0; kt < NT; kt++) {
        CP_WAIT1();
        __syncthreads();
        if (kt + 2 < NT) {
            uint32_t so = ((kt + 2) % 3) * GST;
#pragma unroll
            for (int i = 0; i < 12; i++) cpa16(dstb[i] + so, srcb[i] + (kt + 2) * 64);
        }
        CP_COMMIT();

        uint32_t st = sb + (kt % 3) * GST;
        uint32_t arow = st + (wm * 64 + (lane & 15)) * GROW + ((lane >> 4) << 4);
        uint32_t brow = st + 2 * GTILE +
                        (wn * 32 + (lane & 7) + ((lane >> 4) << 3)) * GROW +
                        (((lane >> 3) & 1) << 4);
#pragma unroll
        for (int kf = 0; kf < 4; kf++) {
            uint32_t ah[4][4], al[4][4];
#pragma unroll
            for (int mi = 0; mi < 4; mi++) {
                ldm4(ah[mi], arow + mi * 16 * GROW + kf * 32);
                ldm4(al[mi], arow + GTILE + mi * 16 * GROW + kf * 32);
            }
#pragma unroll
            for (int njp = 0; njp < 2; njp++) {
                uint32_t bh[4];
                ldm4(bh, brow + njp * 16 * GROW + kf * 32);
#pragma unroll
                for (int mi = 0; mi < 4; mi++) {
                    mma16816(acc[mi][2 * njp],     ah[mi], bh);
                    mma16816(acc[mi][2 * njp],     al[mi], bh);
                    mma16816(acc[mi][2 * njp + 1], ah[mi], bh + 2);
                    mma16816(acc[mi][2 * njp + 1], al[mi], bh + 2);
                }
            }
        }
    }

#pragma unroll
    for (int mi = 0; mi < 4; mi++) {
        size_t r0 = bm + wm * 64 + mi * 16 + (lane >> 2);
        size_t r1 = r0 + 8;
        int p0 = 0, p1 = 0;
        if (MODE == 1 || MODE == 2) {
            p0 = pos[Asel ? Asel[r0] : (int)r0];
            p1 = pos[Asel ? Asel[r1] : (int)r1];
        }
#pragma unroll
        for (int nj = 0; nj < 4; nj++) {
            size_t cc = bn + wn * 32 + nj * 8 + (lane & 3) * 2;
            float a0 = acc[mi][nj][0], b0 = acc[mi][nj][1];
            float a1 = acc[mi][nj][2], b1 = acc[mi][nj][3];
            if (MODE == 0) {
                *(float2*)&Cf[r0 * N + cc] = make_float2(a0, b0);
                *(float2*)&Cf[r1 * N + cc] = make_float2(a1, b1);
            } else if (MODE == 3) {
                *(__half2*)&Oh[r0 * N + cc] = __floats2half2_rn(a0, b0);
                *(__half2*)&Oh[r1 * N + cc] = __floats2half2_rn(a1, b1);
            } else {
                int j = ((int)cc & 127) >> 1;
                float c0 = g_cos[p0 * 64 + j], s0 = g_sin[p0 * 64 + j];
                float c1 = g_cos[p1 * 64 + j], s1 = g_sin[p1 * 64 + j];
                float e0 = a0 * c0 - b0 * s0, o0 = b0 * c0 + a0 * s0;
                float e1 = a1 * c1 - b1 * s1, o1 = b1 * c1 + a1 * s1;
                if (MODE == 1) {
                    uint32_t h, l;
                    split2h(e0, o0, h, l);
                    *(uint32_t*)&Oh[r0 * N + cc] = h;
                    *(uint32_t*)&Ol[r0 * N + cc] = l;
                    split2h(e1, o1, h, l);
                    *(uint32_t*)&Oh[r1 * N + cc] = h;
                    *(uint32_t*)&Ol[r1 * N + cc] = l;
                } else {
                    *(__half2*)&Oh[r0 * N + cc] = __floats2half2_rn(e0, o0);
                    *(__half2*)&Oh[r1 * N + cc] = __floats2half2_rn(e1, o1);
                }
            }
        }
    }
}

// ---------------- HMMA flash attention: 64q x 64k, 4 warps -------------------
#define ATQ 272
#define S_QH 0
#define S_QL 17408
#define S_K  34816
#define S_V  52224
#define ATTN_SMEM 69632

__global__ __launch_bounds__(128) void attn_kernel(
    const __half* __restrict__ Qh, const __half* __restrict__ Ql,
    const __half* __restrict__ Kh, const __half* __restrict__ Vh,
    __half* __restrict__ Yh, __half* __restrict__ Yl) {
    extern __shared__ __align__(128) char ash[];
    uint32_t sb = smem_u32(ash);
    int tid = threadIdx.x, lane = tid & 31, w = tid >> 5;
    int qb = blockIdx.x * 64, h = blockIdx.y, b = blockIdx.z;
    size_t tok0 = (size_t)b * TQn + qb;
    size_t ktok0 = (size_t)b * Tn;
    int hcol = h * 128;
    const float NI = neginf();
    const float scale = 0.08838834764831845f;
    const int nk = g_nkeep[b];
    const int nt = (nk + 63) >> 6;

#pragma unroll
    for (int i = 0; i < 16; i++) {
        int id = tid + i * 128;
        int buf = id >> 10, ww = id & 1023, row = ww >> 4, c = ww & 15;
        const __half* src = (buf ? Ql : Qh) + (tok0 + row) * HDn + hcol + c * 8;
        *(uint4*)(ash + (buf ? S_QL : S_QH) + row * ATQ + c * 16) = *(const uint4*)src;
    }
    __syncthreads();

    uint32_t qhf[8][4], qlf[8][4];
    {
        uint32_t abase = sb + (w * 16 + (lane & 15)) * ATQ + ((lane >> 4) << 4);
#pragma unroll
        for (int kf = 0; kf < 8; kf++) {
            ldm4(qhf[kf], abase + kf * 32);
            ldm4(qlf[kf], abase + S_QL + kf * 32);
        }
    }

    float oa[16][4];
#pragma unroll
    for (int i = 0; i < 16; i++)
#pragma unroll
        for (int j = 0; j < 4; j++) oa[i][j] = 0.f;
    float m_a = NI, m_b = NI, l_a = 0.f, l_b = 0.f;

    int crow = tid >> 4, ccol = tid & 15;
    uint32_t kdst = sb + S_K + crow * ATQ + ccol * 16;
    uint32_t vdst = sb + S_V + crow * ATQ + ccol * 16;
    const __half* ksrc0 = Kh + (ktok0 + crow) * HDn + hcol + ccol * 8;
    const __half* vsrc0 = Vh + (ktok0 + crow) * HDn + hcol + ccol * 8;

#define ISSUE_K(kt) do { \
    const __half* _s = ksrc0 + (size_t)(kt) * 64 * HDn; \
    _Pragma("unroll") for (int _i = 0; _i < 8; _i++) \
        cpa16(kdst + _i * 8 * ATQ, _s + (size_t)_i * 8 * HDn); \
} while (0)
#define ISSUE_V(kt) do { \
    const __half* _s = vsrc0 + (size_t)(kt) * 64 * HDn; \
    _Pragma("unroll") for (int _i = 0; _i < 8; _i++) \
        cpa16(vdst + _i * 8 * ATQ, _s + (size_t)_i * 8 * HDn); \
} while (0)

    ISSUE_K(0); CP_COMMIT();
    ISSUE_V(0); CP_COMMIT();

    for (int kt = 0; kt < nt; kt++) {
        CP_WAIT1();
        __syncthreads();

        // S = Q K^T
        float sc[8][4];
#pragma unroll
        for (int i = 0; i < 8; i++)
#pragma unroll
            for (int j = 0; j < 4; j++) sc[i][j] = 0.f;
        {
            uint32_t bbase = sb + S_K +
                ((lane & 7) + ((lane >> 4) << 3)) * ATQ + (((lane >> 3) & 1) << 4);
#pragma unroll
            for (int kf = 0; kf < 8; kf++) {
#pragma unroll
                for (int njp = 0; njp < 4; njp++) {
                    uint32_t kh4[4];
                    ldm4(kh4, bbase + njp * 16 * ATQ + kf * 32);
                    mma16816(sc[2 * njp],     qhf[kf], kh4);
                    mma16816(sc[2 * njp],     qlf[kf], kh4);
                    mma16816(sc[2 * njp + 1], qhf[kf], kh4 + 2);
                    mma16816(sc[2 * njp + 1], qlf[kf], kh4 + 2);
                }
            }
        }
        __syncthreads();
        ISSUE_K((kt + 1) & 31); CP_COMMIT();

        // validity from compaction (register compare)
        float ta = NI, tb = NI;
        bool v0[8], v1[8];
#pragma unroll
        for (int nf = 0; nf < 8; nf++) {
            int key0 = kt * 64 + nf * 8 + ((lane & 3) << 1);
            v0[nf] = key0 < nk;
            v1[nf] = key0 + 1 < nk;
#pragma unroll
            for (int j = 0; j < 4; j++) sc[nf][j] *= scale;
            if (v0[nf]) { ta = fmaxf(ta, sc[nf][0]); tb = fmaxf(tb, sc[nf][2]); }
            if (v1[nf]) { ta = fmaxf(ta, sc[nf][1]); tb = fmaxf(tb, sc[nf][3]); }
        }
        ta = fmaxf(ta, __shfl_xor_sync(0xffffffffu, ta, 1));
        ta = fmaxf(ta, __shfl_xor_sync(0xffffffffu, ta, 2));
        tb = fmaxf(tb, __shfl_xor_sync(0xffffffffu, tb, 1));
        tb = fmaxf(tb, __shfl_xor_sync(0xffffffffu, tb, 2));
        float mna = fmaxf(m_a, ta), mnb = fmaxf(m_b, tb);
        float alpha_a = (m_a > NI) ? __expf(m_a - mna) : 1.f;
        float alpha_b = (m_b > NI) ? __expf(m_b - mnb) : 1.f;
        m_a = mna; m_b = mnb;

        float sa = 0.f, sbm = 0.f;
#pragma unroll
        for (int nf = 0; nf < 8; nf++) {
            float p0 = (!v0[nf] || m_a == NI) ? 0.f : __expf(sc[nf][0] - m_a);
            float p1 = (!v1[nf] || m_a == NI) ? 0.f : __expf(sc[nf][1] - m_a);
            float p2 = (!v0[nf] || m_b == NI) ? 0.f : __expf(sc[nf][2] - m_b);
            float p3 = (!v1[nf] || m_b == NI) ? 0.f : __expf(sc[nf][3] - m_b);
            sc[nf][0] = p0; sc[nf][1] = p1; sc[nf][2] = p2; sc[nf][3] = p3;
            sa += p0 + p1; sbm += p2 + p3;
        }
        sa  += __shfl_xor_sync(0xffffffffu, sa, 1);
        sa  += __shfl_xor_sync(0xffffffffu, sa, 2);
        sbm += __shfl_xor_sync(0xffffffffu, sbm, 1);
        sbm += __shfl_xor_sync(0xffffffffu, sbm, 2);
        l_a = l_a * alpha_a + sa;
        l_b = l_b * alpha_b + sbm;
#pragma unroll
        for (int nf = 0; nf < 16; nf++) {
            oa[nf][0] *= alpha_a; oa[nf][1] *= alpha_a;
            oa[nf][2] *= alpha_b; oa[nf][3] *= alpha_b;
        }

        uint32_t ph[4][4], pl[4][4];
#pragma unroll
        for (int t = 0; t < 4; t++) {
            split2h(sc[2 * t][0],     sc[2 * t][1],     ph[t][0], pl[t][0]);
            split2h(sc[2 * t][2],     sc[2 * t][3],     ph[t][1], pl[t][1]);
            split2h(sc[2 * t + 1][0], sc[2 * t + 1][1], ph[t][2], pl[t][2]);
            split2h(sc[2 * t + 1][2], sc[2 * t + 1][3], ph[t][3], pl[t][3]);
        }

        CP_WAIT1();
        __syncthreads();

        // O += P V
        {
            uint32_t vbase = sb + S_V +
                ((lane & 7) + (((lane >> 3) & 1) << 3)) * ATQ + ((lane >> 4) << 4);
#pragma unroll
            for (int t = 0; t < 4; t++) {
#pragma unroll
                for (int njp = 0; njp < 8; njp++) {
                    uint32_t vh4[4];
                    ldm4t(vh4, vbase + t * 16 * ATQ + njp * 32);
                    int n0 = njp * 2, n1 = n0 + 1;
                    mma16816(oa[n0], ph[t], vh4);
                    mma16816(oa[n0], pl[t], vh4);
                    mma16816(oa[n1], ph[t], vh4 + 2);
                    mma16816(oa[n1], pl[t], vh4 + 2);
                }
            }
        }
        __syncthreads();
        ISSUE_V((kt + 1) & 31); CP_COMMIT();
    }

    float ia = 1.f / l_a, ib = 1.f / l_b;
    size_t ra = (tok0 + w * 16 + (lane >> 2)) * HDn + hcol + (lane & 3) * 2;
#pragma unroll
    for (int nf = 0; nf < 16; nf++) {
        uint32_t hh, ll;
        split2h(oa[nf][0] * ia, oa[nf][1] * ia, hh, ll);
        *(uint32_t*)&Yh[ra + nf * 8] = hh;
        *(uint32_t*)&Yl[ra + nf * 8] = ll;
        split2h(oa[nf][2] * ib, oa[nf][3] * ib, hh, ll);
        *(uint32_t*)&Yh[ra + 8 * HDn + nf * 8] = hh;
        *(uint32_t*)&Yl[ra + 8 * HDn + nf * 8] = ll;
    }
}

// ---------------- launch -----------------------------------------------------
extern "C" void kernel_launch(void* const* d_in, const int* in_sizes, int n_in,
                              void* d_out, int out_size) {
    const float* x       = (const float*)d_in[0];
    const float* xall    = (const float*)d_in[1];
    const int*   posx    = (const int*)d_in[2];
    const int*   posxall = (const int*)d_in[3];
    const void*  mask    = d_in[4];
    const float* Wq      = (const float*)d_in[5];
    const float* Wk      = (const float*)d_in[6];
    const float* Wv      = (const float*)d_in[7];
    const float* Wo      = (const float*)d_in[8];
    float* out = (float*)d_out;

    __half *xh, *xl, *ah, *al, *qh, *ql, *kh, *vh, *yh, *yl, *wq, *wk, *wv, *wo;
    int *sel, *nkp;
    cudaGetSymbolAddress((void**)&xh, g_xh);
    cudaGetSymbolAddress((void**)&xl, g_xl);
    cudaGetSymbolAddress((void**)&ah, g_ah);
    cudaGetSymbolAddress((void**)&al, g_al);
    cudaGetSymbolAddress((void**)&qh, g_qh);
    cudaGetSymbolAddress((void**)&ql, g_ql);
    cudaGetSymbolAddress((void**)&kh, g_kh);
    cudaGetSymbolAddress((void**)&vh, g_vh);
    cudaGetSymbolAddress((void**)&yh, g_yh);
    cudaGetSymbolAddress((void**)&yl, g_yl);
    cudaGetSymbolAddress((void**)&wq, g_wq);
    cudaGetSymbolAddress((void**)&wk, g_wk);
    cudaGetSymbolAddress((void**)&wv, g_wv);
    cudaGetSymbolAddress((void**)&wo, g_wo);
    cudaGetSymbolAddress((void**)&sel, g_sel);
    cudaGetSymbolAddress((void**)&nkp, g_nkeep);

    cudaFuncSetAttribute(bgemm_kernel<0>, cudaFuncAttributeMaxDynamicSharedMemorySize, GSMEM);
    cudaFuncSetAttribute(bgemm_kernel<1>, cudaFuncAttributeMaxDynamicSharedMemorySize, GSMEM);
    cudaFuncSetAttribute(bgemm_kernel<2>, cudaFuncAttributeMaxDynamicSharedMemorySize, GSMEM);
    cudaFuncSetAttribute(bgemm_kernel<3>, cudaFuncAttributeMaxDynamicSharedMemorySize, GSMEM);
    cudaFuncSetAttribute(attn_kernel, cudaFuncAttributeMaxDynamicSharedMemorySize, ATTN_SMEM);

    // side stream for the input-independent / mask-only prologue
    static cudaStream_t s1 = nullptr;
    static cudaEvent_t ev0 = nullptr, evPre = nullptr;
    if (s1 == nullptr) {
        cudaStreamCreateWithFlags(&s1, cudaStreamNonBlocking);
        cudaEventCreateWithFlags(&ev0,  cudaEventDisableTiming);
        cudaEventCreateWithFlags(&evPre, cudaEventDisableTiming);
    }

    cudaEventRecord(ev0, 0);
    cudaStreamWaitEvent(s1, ev0, 0);
    ropetab_kernel<<<(POSN * 64 + 255) / 256, 256, 0, s1>>>();
    selbuild_kernel<<<Bb, 1024, 0, s1>>>(mask);
    cudaEventRecord(evPre, s1);

    const int NE4 = NTOK * En / 4;
    dim3 gs((NE4 + 511) / 512, 1, 2);
    splitH2x2_kernel<<<gs, 256>>>(x, xall, xh, xl, ah, al, NE4);
    dim3 gt(64, 32, 4), bt(32, 8);
    splitT4_kernel<<<gt, bt>>>(Wq, Wk, Wv, Wo, wq, wk, wv, wo);

    cudaStreamWaitEvent(0, evPre, 0);   // join: rope tables + sel ready

    dim3 gg(HDn / 128, NTOK / 128);
    bgemm_kernel<1><<<gg, 256, GSMEM>>>(xh, xl, wq, nullptr, qh, ql,
                                        nullptr, posx, nullptr, NTOK, HDn, En);
    bgemm_kernel<2><<<gg, 256, GSMEM>>>(ah, al, wk, nullptr, kh, nullptr,
                                        sel, posxall, nkp, NTOK, HDn, En);
    bgemm_kernel<3><<<gg, 256, GSMEM>>>(ah, al, wv, nullptr, vh, nullptr,
                                        sel, nullptr, nkp, NTOK, HDn, En);

    dim3 ga(TQn / 64, Hn, Bb);
    attn_kernel<<<ga, 128, ATTN_SMEM>>>(qh, ql, kh, vh, yh, yl);

    dim3 go(En / 128, NTOK / 128);
    bgemm_kernel<0><<<go, 256, GSMEM>>>(yh, yl, wo, out, nullptr, nullptr,
                                        nullptr, nullptr, nullptr, NTOK, En, HDn);
}